// round 3
// baseline (speedup 1.0000x reference)
#include <cuda_runtime.h>
#include <cuda_bf16.h>

#define GNUM 8
#define DIN 1024
#define DOUT 1024
#define RNK 16
#define SCALEF 2.0f

#define BM 128
#define BN 128
#define BK 8
#define MAX_N 8192
#define MAX_TILES ((MAX_N / BM) + GNUM)   // 72

// ---------------- device scratch (no allocations allowed) ----------------
__device__ int g_tile_row0[MAX_TILES];
__device__ int g_tile_rows[MAX_TILES];
__device__ int g_tile_grp[MAX_TILES];
__device__ __align__(16) float g_Ascr[MAX_N * RNK];   // SCALE * (x @ W_A[g])

// ---------------- helpers ----------------
__device__ __forceinline__ int get_group(const int* p, int i, int is64) {
    // values are tiny (<8); for int64 little-endian the low word suffices
    return is64 ? p[2 * i] : p[i];
}

__device__ __forceinline__ void fma_tile(float (&acc)[2][2][4][4],
                                         float4 a0, float4 a1,
                                         float4 b0, float4 b1) {
    float av[2][4] = {{a0.x, a0.y, a0.z, a0.w}, {a1.x, a1.y, a1.z, a1.w}};
    float bv[2][4] = {{b0.x, b0.y, b0.z, b0.w}, {b1.x, b1.y, b1.z, b1.w}};
#pragma unroll
    for (int ri = 0; ri < 2; ri++)
#pragma unroll
        for (int rj = 0; rj < 2; rj++)
#pragma unroll
            for (int i = 0; i < 4; i++)
#pragma unroll
                for (int j = 0; j < 4; j++)
                    acc[ri][rj][i][j] += av[ri][i] * bv[rj][j];
}

// ---------------- kernel 0: group boundaries + tile list ----------------
__global__ void setup_kernel(const int* __restrict__ groups_raw, int N) {
    __shared__ int start[GNUM + 1];
    __shared__ int is64_s;
    int t = threadIdx.x;
    if (t == 0) {
        // dtype hedge: if the buffer is int64, word N-1 is a high word (== 0)
        // while word N-2 is a genuine low word (almost surely != 0). For int32
        // data word N-1 is the max group (almost surely != 0). All-zero data
        // gives the same answer either way.
        int wlast = groups_raw[N - 1];
        int wprev = groups_raw[N - 2];
        is64_s = (wlast == 0 && wprev != 0) ? 1 : 0;
    }
    __syncthreads();
    int is64 = is64_s;

    if (t <= GNUM) {
        int target = t;
        int lo = 0, hi = N;
        while (lo < hi) {
            int mid = (lo + hi) >> 1;
            if (get_group(groups_raw, mid, is64) < target) lo = mid + 1;
            else hi = mid;
        }
        start[t] = lo;
    }
    __syncthreads();
    if (t == 0) {
        int nt = 0;
        for (int g = 0; g < GNUM; g++) {
            int s = start[g], e = start[g + 1];
            for (int r0 = s; r0 < e; r0 += BM) {
                g_tile_row0[nt] = r0;
                g_tile_rows[nt] = min(BM, e - r0);
                g_tile_grp[nt]  = g;
                nt++;
            }
        }
        for (int i = nt; i < MAX_TILES; i++) g_tile_rows[i] = 0;
    }
}

// ---------------- kernel 1: A_scaled = SCALE * (x @ W_A[g]) ----------------
__global__ __launch_bounds__(256) void lora_a_kernel(const float* __restrict__ x,
                                                     const float* __restrict__ WA) {
    int tile = blockIdx.x;
    int rows = g_tile_rows[tile];
    if (rows == 0) return;
    int row0 = g_tile_row0[tile];
    int grp  = g_tile_grp[tile];

    int t   = threadIdx.x;
    int row = t >> 1;           // 0..127
    int rh  = (t & 1) * 8;      // half of the 16 R-outputs
    bool valid = row < rows;
    const float* xr = x + (size_t)(row0 + (valid ? row : 0)) * DIN;
    const float* wg = WA + (size_t)grp * DIN * RNK;

    __shared__ float Ws[32][RNK];
    float acc[8] = {0.f, 0.f, 0.f, 0.f, 0.f, 0.f, 0.f, 0.f};

    for (int kb = 0; kb < DIN; kb += 32) {
        __syncthreads();
        {
            int lin = t;
            Ws[lin >> 4][lin & 15] = wg[(size_t)(kb + (lin >> 4)) * RNK + (lin & 15)];
            lin = t + 256;
            Ws[lin >> 4][lin & 15] = wg[(size_t)(kb + (lin >> 4)) * RNK + (lin & 15)];
        }
        __syncthreads();
#pragma unroll
        for (int kk = 0; kk < 32; kk++) {
            float xv = xr[kb + kk];
#pragma unroll
            for (int u = 0; u < 8; u++) acc[u] += xv * Ws[kk][rh + u];
        }
    }
    if (valid) {
        float* dst = g_Ascr + (size_t)(row0 + row) * RNK + rh;
#pragma unroll
        for (int u = 0; u < 8; u++) dst[u] = SCALEF * acc[u];
    }
}

// ---------------- kernel 2: main grouped GEMM + fused LoRA epilogue ----------------
__global__ __launch_bounds__(256, 2) void main_gemm(const float* __restrict__ x,
                                                    const float* __restrict__ Wb,
                                                    const float* __restrict__ WBl,
                                                    float* __restrict__ out) {
    int tile = blockIdx.x;
    int rows = g_tile_rows[tile];
    if (rows == 0) return;
    int row0 = g_tile_row0[tile];
    int grp  = g_tile_grp[tile];
    int col0 = blockIdx.y * BN;

    __shared__ float As[BK][BM + 4];    // stride 132 -> conflict-free transposed stores
    __shared__ float Bs[BK][BN];
    __shared__ float LAt[RNK][BM + 4];  // lora A, transposed
    __shared__ float LW[RNK][BN];       // lora B tile

    int t  = threadIdx.x;
    int tx = t & 15;
    int ty = t >> 4;

    // A-tile loads: BMxBK = 256 float4; one per thread
    int arow = t >> 1;
    int ak   = (t & 1) * 4;
    bool arow_ok = arow < rows;
    const float* xA = x + (size_t)(row0 + (arow_ok ? arow : 0)) * DIN + ak;
    // B-tile loads: BKxBN = 256 float4; one per thread
    int bk = t >> 5;
    int bc = (t & 31) * 4;
    const float* wB = Wb + (size_t)grp * DIN * DOUT + (size_t)bk * DOUT + col0 + bc;

    float acc[2][2][4][4] = {};

    const int NIT = DIN / BK;   // 128
    float4 af = arow_ok ? *(const float4*)xA : make_float4(0.f, 0.f, 0.f, 0.f);
    float4 bf = *(const float4*)wB;

    for (int kb = 0; kb < NIT; kb++) {
        // stage current fragments to smem
        As[ak + 0][arow] = af.x;
        As[ak + 1][arow] = af.y;
        As[ak + 2][arow] = af.z;
        As[ak + 3][arow] = af.w;
        *(float4*)&Bs[bk][bc] = bf;
        __syncthreads();

        if (kb + 1 < NIT) {   // prefetch next tile (overlaps with compute below)
            af = arow_ok ? *(const float4*)(xA + (kb + 1) * BK)
                         : make_float4(0.f, 0.f, 0.f, 0.f);
            bf = *(const float4*)(wB + (size_t)(kb + 1) * BK * DOUT);
        }

#pragma unroll
        for (int kk = 0; kk < BK; kk++) {
            float4 a0 = *(const float4*)&As[kk][ty * 4];
            float4 a1 = *(const float4*)&As[kk][64 + ty * 4];
            float4 b0 = *(const float4*)&Bs[kk][tx * 4];
            float4 b1 = *(const float4*)&Bs[kk][64 + tx * 4];
            fma_tile(acc, a0, a1, b0, b1);
        }
        __syncthreads();
    }

    // ---- fused LoRA epilogue: acc += A_scaled[tile rows] @ W_B[grp][:, cols] ----
#pragma unroll
    for (int it = 0; it < 2; it++) {
        int lin = t + it * 256;              // 0..511
        int m   = lin >> 2;                  // row within tile
        int rq  = (lin & 3) * 4;             // 4 consecutive r
        float4 v = (m < rows) ? *(const float4*)(g_Ascr + (size_t)(row0 + m) * RNK + rq)
                              : make_float4(0.f, 0.f, 0.f, 0.f);
        LAt[rq + 0][m] = v.x;
        LAt[rq + 1][m] = v.y;
        LAt[rq + 2][m] = v.z;
        LAt[rq + 3][m] = v.w;
    }
    {
        const float* wl = WBl + (size_t)grp * RNK * DOUT + col0;
#pragma unroll
        for (int it = 0; it < 2; it++) {
            int lin = t + it * 256;
            int r = lin >> 5;
            int c = (lin & 31) * 4;
            *(float4*)&LW[r][c] = *(const float4*)(wl + (size_t)r * DOUT + c);
        }
    }
    __syncthreads();

#pragma unroll
    for (int r = 0; r < RNK; r++) {
        float4 a0 = *(const float4*)&LAt[r][ty * 4];
        float4 a1 = *(const float4*)&LAt[r][64 + ty * 4];
        float4 b0 = *(const float4*)&LW[r][tx * 4];
        float4 b1 = *(const float4*)&LW[r][64 + tx * 4];
        fma_tile(acc, a0, a1, b0, b1);
    }

    // ---- store (each output element written exactly once across the grid) ----
#pragma unroll
    for (int ri = 0; ri < 2; ri++)
#pragma unroll
        for (int i = 0; i < 4; i++) {
            int m = ri * 64 + ty * 4 + i;
            if (m < rows) {
                float* p = out + (size_t)(row0 + m) * DOUT + col0;
                *(float4*)(p + tx * 4) =
                    make_float4(acc[ri][0][i][0], acc[ri][0][i][1],
                                acc[ri][0][i][2], acc[ri][0][i][3]);
                *(float4*)(p + 64 + tx * 4) =
                    make_float4(acc[ri][1][i][0], acc[ri][1][i][1],
                                acc[ri][1][i][2], acc[ri][1][i][3]);
            }
        }
}

// ---------------- launch ----------------
extern "C" void kernel_launch(void* const* d_in, const int* in_sizes, int n_in,
                              void* d_out, int out_size) {
    const float* x   = (const float*)d_in[0];
    const int*   xg  = (const int*)d_in[1];   // x_groups (int32, int64-hedged)
    const float* Wb  = (const float*)d_in[2]; // [G, DIN, DOUT]
    const float* WA  = (const float*)d_in[3]; // [G, DIN, R]
    const float* WBl = (const float*)d_in[4]; // [G, R, DOUT]
    float* out = (float*)d_out;

    int N = in_sizes[0] / DIN;
    int maxTiles = (N + BM - 1) / BM + GNUM;

    setup_kernel<<<1, 32>>>(xg, N);
    lora_a_kernel<<<maxTiles, 256>>>(x, WA);
    dim3 grid(maxTiles, DOUT / BN);
    main_gemm<<<grid, 256>>>(x, Wb, WBl, out);
}

// round 4
// speedup vs baseline: 1.0039x; 1.0039x over previous
#include <cuda_runtime.h>
#include <cuda_bf16.h>

#define GNUM 8
#define DIN 1024
#define DOUT 1024
#define RNK 16
#define SCALEF 2.0f

#define BM 128
#define BN 128
#define BK 8
#define MAX_N 8192
#define MAX_TILES ((MAX_N / BM) + GNUM)   // 72

// ---------------- device scratch (no allocations allowed) ----------------
__device__ int g_tile_row0[MAX_TILES];
__device__ int g_tile_rows[MAX_TILES];
__device__ int g_tile_grp[MAX_TILES];
__device__ __align__(16) float g_Ascr[MAX_N * RNK];   // SCALE * (x @ W_A[g])

// ---------------- helpers ----------------
__device__ __forceinline__ int get_group(const int* p, int i, int is64) {
    // values are tiny (<8); for int64 little-endian the low word suffices
    return is64 ? p[2 * i] : p[i];
}

__device__ __forceinline__ void fma_tile(float (&acc)[2][2][4][4],
                                         float4 a0, float4 a1,
                                         float4 b0, float4 b1) {
    float av[2][4] = {{a0.x, a0.y, a0.z, a0.w}, {a1.x, a1.y, a1.z, a1.w}};
    float bv[2][4] = {{b0.x, b0.y, b0.z, b0.w}, {b1.x, b1.y, b1.z, b1.w}};
#pragma unroll
    for (int ri = 0; ri < 2; ri++)
#pragma unroll
        for (int rj = 0; rj < 2; rj++)
#pragma unroll
            for (int i = 0; i < 4; i++)
#pragma unroll
                for (int j = 0; j < 4; j++)
                    acc[ri][rj][i][j] += av[ri][i] * bv[rj][j];
}

// ---------------- kernel 0: group boundaries + tile list ----------------
__global__ void setup_kernel(const int* __restrict__ groups_raw, int N) {
    __shared__ int start[GNUM + 1];
    __shared__ int is64_s;
    int t = threadIdx.x;
    if (t == 0) {
        // dtype hedge: if the buffer is int64, word N-1 is a high word (== 0)
        // while word N-2 is a genuine low word (almost surely != 0). For int32
        // data word N-1 is the max group (almost surely != 0). All-zero data
        // gives the same answer either way.
        int wlast = groups_raw[N - 1];
        int wprev = groups_raw[N - 2];
        is64_s = (wlast == 0 && wprev != 0) ? 1 : 0;
    }
    __syncthreads();
    int is64 = is64_s;

    if (t <= GNUM) {
        int target = t;
        int lo = 0, hi = N;
        while (lo < hi) {
            int mid = (lo + hi) >> 1;
            if (get_group(groups_raw, mid, is64) < target) lo = mid + 1;
            else hi = mid;
        }
        start[t] = lo;
    }
    __syncthreads();
    if (t == 0) {
        int nt = 0;
        for (int g = 0; g < GNUM; g++) {
            int s = start[g], e = start[g + 1];
            for (int r0 = s; r0 < e; r0 += BM) {
                g_tile_row0[nt] = r0;
                g_tile_rows[nt] = min(BM, e - r0);
                g_tile_grp[nt]  = g;
                nt++;
            }
        }
        for (int i = nt; i < MAX_TILES; i++) g_tile_rows[i] = 0;
    }
}

// ---------------- kernel 1: A_scaled = SCALE * (x @ W_A[g]) ----------------
__global__ __launch_bounds__(256) void lora_a_kernel(const float* __restrict__ x,
                                                     const float* __restrict__ WA) {
    int tile = blockIdx.x;
    int rows = g_tile_rows[tile];
    if (rows == 0) return;
    int row0 = g_tile_row0[tile];
    int grp  = g_tile_grp[tile];

    int t   = threadIdx.x;
    int row = t >> 1;           // 0..127
    int rh  = (t & 1) * 8;      // half of the 16 R-outputs
    bool valid = row < rows;
    const float* xr = x + (size_t)(row0 + (valid ? row : 0)) * DIN;
    const float* wg = WA + (size_t)grp * DIN * RNK;

    __shared__ float Ws[32][RNK];
    float acc[8] = {0.f, 0.f, 0.f, 0.f, 0.f, 0.f, 0.f, 0.f};

    for (int kb = 0; kb < DIN; kb += 32) {
        __syncthreads();
        {
            int lin = t;
            Ws[lin >> 4][lin & 15] = wg[(size_t)(kb + (lin >> 4)) * RNK + (lin & 15)];
            lin = t + 256;
            Ws[lin >> 4][lin & 15] = wg[(size_t)(kb + (lin >> 4)) * RNK + (lin & 15)];
        }
        __syncthreads();
#pragma unroll
        for (int kk = 0; kk < 32; kk++) {
            float xv = xr[kb + kk];
#pragma unroll
            for (int u = 0; u < 8; u++) acc[u] += xv * Ws[kk][rh + u];
        }
    }
    if (valid) {
        float* dst = g_Ascr + (size_t)(row0 + row) * RNK + rh;
#pragma unroll
        for (int u = 0; u < 8; u++) dst[u] = SCALEF * acc[u];
    }
}

// ---------------- kernel 2: main grouped GEMM + fused LoRA epilogue ----------------
__global__ __launch_bounds__(256, 2) void main_gemm(const float* __restrict__ x,
                                                    const float* __restrict__ Wb,
                                                    const float* __restrict__ WBl,
                                                    float* __restrict__ out) {
    int tile = blockIdx.x;
    int rows = g_tile_rows[tile];
    if (rows == 0) return;
    int row0 = g_tile_row0[tile];
    int grp  = g_tile_grp[tile];
    int col0 = blockIdx.y * BN;

    __shared__ float As[BK][BM + 4];    // stride 132 -> conflict-free transposed stores
    __shared__ float Bs[BK][BN];
    __shared__ float LAt[RNK][BM + 4];  // lora A, transposed
    __shared__ float LW[RNK][BN];       // lora B tile

    int t  = threadIdx.x;
    int tx = t & 15;
    int ty = t >> 4;

    // A-tile loads: BMxBK = 256 float4; one per thread
    int arow = t >> 1;
    int ak   = (t & 1) * 4;
    bool arow_ok = arow < rows;
    const float* xA = x + (size_t)(row0 + (arow_ok ? arow : 0)) * DIN + ak;
    // B-tile loads: BKxBN = 256 float4; one per thread
    int bk = t >> 5;
    int bc = (t & 31) * 4;
    const float* wB = Wb + (size_t)grp * DIN * DOUT + (size_t)bk * DOUT + col0 + bc;

    float acc[2][2][4][4] = {};

    const int NIT = DIN / BK;   // 128
    float4 af = arow_ok ? *(const float4*)xA : make_float4(0.f, 0.f, 0.f, 0.f);
    float4 bf = *(const float4*)wB;

    for (int kb = 0; kb < NIT; kb++) {
        // stage current fragments to smem
        As[ak + 0][arow] = af.x;
        As[ak + 1][arow] = af.y;
        As[ak + 2][arow] = af.z;
        As[ak + 3][arow] = af.w;
        *(float4*)&Bs[bk][bc] = bf;
        __syncthreads();

        if (kb + 1 < NIT) {   // prefetch next tile (overlaps with compute below)
            af = arow_ok ? *(const float4*)(xA + (kb + 1) * BK)
                         : make_float4(0.f, 0.f, 0.f, 0.f);
            bf = *(const float4*)(wB + (size_t)(kb + 1) * BK * DOUT);
        }

#pragma unroll
        for (int kk = 0; kk < BK; kk++) {
            float4 a0 = *(const float4*)&As[kk][ty * 4];
            float4 a1 = *(const float4*)&As[kk][64 + ty * 4];
            float4 b0 = *(const float4*)&Bs[kk][tx * 4];
            float4 b1 = *(const float4*)&Bs[kk][64 + tx * 4];
            fma_tile(acc, a0, a1, b0, b1);
        }
        __syncthreads();
    }

    // ---- fused LoRA epilogue: acc += A_scaled[tile rows] @ W_B[grp][:, cols] ----
#pragma unroll
    for (int it = 0; it < 2; it++) {
        int lin = t + it * 256;              // 0..511
        int m   = lin >> 2;                  // row within tile
        int rq  = (lin & 3) * 4;             // 4 consecutive r
        float4 v = (m < rows) ? *(const float4*)(g_Ascr + (size_t)(row0 + m) * RNK + rq)
                              : make_float4(0.f, 0.f, 0.f, 0.f);
        LAt[rq + 0][m] = v.x;
        LAt[rq + 1][m] = v.y;
        LAt[rq + 2][m] = v.z;
        LAt[rq + 3][m] = v.w;
    }
    {
        const float* wl = WBl + (size_t)grp * RNK * DOUT + col0;
#pragma unroll
        for (int it = 0; it < 2; it++) {
            int lin = t + it * 256;
            int r = lin >> 5;
            int c = (lin & 31) * 4;
            *(float4*)&LW[r][c] = *(const float4*)(wl + (size_t)r * DOUT + c);
        }
    }
    __syncthreads();

#pragma unroll
    for (int r = 0; r < RNK; r++) {
        float4 a0 = *(const float4*)&LAt[r][ty * 4];
        float4 a1 = *(const float4*)&LAt[r][64 + ty * 4];
        float4 b0 = *(const float4*)&LW[r][tx * 4];
        float4 b1 = *(const float4*)&LW[r][64 + tx * 4];
        fma_tile(acc, a0, a1, b0, b1);
    }

    // ---- store (each output element written exactly once across the grid) ----
#pragma unroll
    for (int ri = 0; ri < 2; ri++)
#pragma unroll
        for (int i = 0; i < 4; i++) {
            int m = ri * 64 + ty * 4 + i;
            if (m < rows) {
                float* p = out + (size_t)(row0 + m) * DOUT + col0;
                *(float4*)(p + tx * 4) =
                    make_float4(acc[ri][0][i][0], acc[ri][0][i][1],
                                acc[ri][0][i][2], acc[ri][0][i][3]);
                *(float4*)(p + 64 + tx * 4) =
                    make_float4(acc[ri][1][i][0], acc[ri][1][i][1],
                                acc[ri][1][i][2], acc[ri][1][i][3]);
            }
        }
}

// ---------------- launch ----------------
extern "C" void kernel_launch(void* const* d_in, const int* in_sizes, int n_in,
                              void* d_out, int out_size) {
    const float* x   = (const float*)d_in[0];
    const int*   xg  = (const int*)d_in[1];   // x_groups (int32, int64-hedged)
    const float* Wb  = (const float*)d_in[2]; // [G, DIN, DOUT]
    const float* WA  = (const float*)d_in[3]; // [G, DIN, R]
    const float* WBl = (const float*)d_in[4]; // [G, R, DOUT]
    float* out = (float*)d_out;

    int N = in_sizes[0] / DIN;
    int maxTiles = (N + BM - 1) / BM + GNUM;

    setup_kernel<<<1, 32>>>(xg, N);
    lora_a_kernel<<<maxTiles, 256>>>(x, WA);
    dim3 grid(maxTiles, DOUT / BN);
    main_gemm<<<grid, 256>>>(x, Wb, WBl, out);
}

// round 7
// speedup vs baseline: 1.5086x; 1.5027x over previous
#include <cuda_runtime.h>
#include <cuda_bf16.h>
#include <cstdint>

#define GNUM 8
#define DIN 1024
#define DOUT 1024
#define RNK 16
#define SCALEF 2.0f

#define BM 128
#define BN 128
#define KC 64                 // bf16 K elements per chunk
#define NCHUNK 17             // 16 real K-chunks + 1 LoRA chunk
#define MAX_N 8192
#define MAX_TILES ((MAX_N / BM) + GNUM)   // 72
#define CHUNK_U4 1024         // 16KB per tile-chunk image (128x64 bf16), in uint4

// smem layout: per stage 4 matrices (A_hi, A_lo, B_hi, B_lo), each 128 rows x 144B
#define ROWB 144
#define MAT_B (128 * ROWB)            // 18432
#define STAGE_B (4 * MAT_B)           // 73728
#define SMEM_MAIN (2 * STAGE_B)       // 147456

// ---------------- device scratch (no allocations allowed) ----------------
__device__ int g_tile_row0[MAX_TILES];
__device__ int g_tile_rows[MAX_TILES];
__device__ int g_tile_grp[MAX_TILES];
__device__ __align__(16) float g_Ascr[MAX_N * RNK];
__device__ uint4 gA_hi[MAX_TILES * NCHUNK * CHUNK_U4];
__device__ uint4 gA_lo[MAX_TILES * NCHUNK * CHUNK_U4];
__device__ uint4 gB_hi[GNUM * 8 * NCHUNK * CHUNK_U4];
__device__ uint4 gB_lo[GNUM * 8 * NCHUNK * CHUNK_U4];

// ---------------- PTX helpers (baseline ISA only; no 'a'-features) ----------------
__device__ __forceinline__ uint32_t smem_u32(const void* p) {
    uint32_t a;
    asm("{ .reg .u64 t; cvta.to.shared.u64 t, %1; cvt.u32.u64 %0, t; }" : "=r"(a) : "l"(p));
    return a;
}
#define CP_ASYNC16(dst, src) \
    asm volatile("cp.async.cg.shared.global [%0], [%1], 16;" :: "r"(dst), "l"(src) : "memory")
#define CP_COMMIT() asm volatile("cp.async.commit_group;" ::: "memory")
#define CP_WAIT1()  asm volatile("cp.async.wait_group 1;" ::: "memory")

__device__ __forceinline__ void ldm_x4(uint32_t* r, uint32_t addr) {
    asm volatile("ldmatrix.sync.aligned.m8n8.x4.shared.b16 {%0,%1,%2,%3}, [%4];"
                 : "=r"(r[0]), "=r"(r[1]), "=r"(r[2]), "=r"(r[3]) : "r"(addr));
}
__device__ __forceinline__ void mma_bf16(float* d, const uint32_t* a, uint32_t b0, uint32_t b1) {
    asm volatile("mma.sync.aligned.m16n8k16.row.col.f32.bf16.bf16.f32 "
                 "{%0,%1,%2,%3}, {%4,%5,%6,%7}, {%8,%9}, {%0,%1,%2,%3};"
                 : "+f"(d[0]), "+f"(d[1]), "+f"(d[2]), "+f"(d[3])
                 : "r"(a[0]), "r"(a[1]), "r"(a[2]), "r"(a[3]), "r"(b0), "r"(b1));
}

// ---------------- hi/lo bf16 split ----------------
__device__ __forceinline__ void hilo8(const float* v, uint4& hi, uint4& lo) {
    uint32_t h[4], l[4];
#pragma unroll
    for (int p = 0; p < 4; p++) {
        float a = v[2 * p], b = v[2 * p + 1];
        __nv_bfloat16 ha = __float2bfloat16(a), hb = __float2bfloat16(b);
        float ra = __bfloat162float(ha), rb = __bfloat162float(hb);
        __nv_bfloat16 la = __float2bfloat16(a - ra), lb = __float2bfloat16(b - rb);
        __nv_bfloat162 hp; hp.x = ha; hp.y = hb;
        __nv_bfloat162 lp; lp.x = la; lp.y = lb;
        h[p] = *reinterpret_cast<uint32_t*>(&hp);
        l[p] = *reinterpret_cast<uint32_t*>(&lp);
    }
    hi = make_uint4(h[0], h[1], h[2], h[3]);
    lo = make_uint4(l[0], l[1], l[2], l[3]);
}

// row-major [row][64k] bf16 image, uint4 index = row*8 + kq/8
__device__ __forceinline__ void write_img(uint4* bh, uint4* bl, int row, int kq,
                                          const float* v) {
    uint32_t s = (uint32_t)row * 8u + ((uint32_t)kq >> 3);
    uint4 hi, lo;
    hilo8(v, hi, lo);
    bh[s] = hi;
    bl[s] = lo;
}

__device__ __forceinline__ int get_group(const int* p, int i, int is64) {
    return is64 ? p[2 * i] : p[i];
}

// ---------------- kernel 0: group boundaries + tile list ----------------
__global__ void setup_kernel(const int* __restrict__ gr, int N) {
    __shared__ int start[GNUM + 1];
    __shared__ int is64_s;
    int t = threadIdx.x;
    if (t == 0) {
        int wl = gr[N - 1], wp = gr[N - 2];
        is64_s = (wl == 0 && wp != 0) ? 1 : 0;
    }
    if (t < GNUM) start[t] = -1;
    if (t == GNUM) start[GNUM] = N;
    __syncthreads();
    int is64 = is64_s;
    int per = (N + 255) >> 8;
    int b = t * per, e = min(N, b + per);
    if (b < N) {
        int gp = (b == 0) ? -1 : get_group(gr, b - 1, is64);
        for (int i = b; i < e; i++) {
            int g = get_group(gr, i, is64);
            if (g != gp) {
                for (int gg = gp + 1; gg <= g; gg++) start[gg] = i;
                gp = g;
            }
        }
    }
    __syncthreads();
    if (t == 0) {
        for (int g = GNUM - 1; g >= 0; g--)
            if (start[g] < 0) start[g] = start[g + 1];
        int nt = 0;
        for (int g = 0; g < GNUM; g++) {
            int s = start[g], e2 = start[g + 1];
            for (int r0 = s; r0 < e2; r0 += BM) {
                g_tile_row0[nt] = r0;
                g_tile_rows[nt] = min(BM, e2 - r0);
                g_tile_grp[nt]  = g;
                nt++;
            }
        }
        for (int i = nt; i < MAX_TILES; i++) g_tile_rows[i] = 0;
    }
}

// ---------------- kernel 1: A_scaled = SCALE * (x @ W_A[g]) ----------------
__global__ __launch_bounds__(256) void lora_a_kernel(const float* __restrict__ x,
                                                     const float* __restrict__ WA) {
    int tile = blockIdx.x;
    int rows = g_tile_rows[tile];
    if (rows == 0) return;
    int row0 = g_tile_row0[tile];
    int grp  = g_tile_grp[tile];

    int t   = threadIdx.x;
    int row = t >> 1;
    int rh  = (t & 1) * 8;
    bool valid = row < rows;
    const float* xr = x + (size_t)(row0 + (valid ? row : 0)) * DIN;
    const float* wg = WA + (size_t)grp * DIN * RNK;

    __shared__ float Ws[32][RNK];
    float acc[8] = {0.f, 0.f, 0.f, 0.f, 0.f, 0.f, 0.f, 0.f};

    for (int kb = 0; kb < DIN; kb += 32) {
        __syncthreads();
        {
            int lin = t;
            Ws[lin >> 4][lin & 15] = wg[(size_t)(kb + (lin >> 4)) * RNK + (lin & 15)];
            lin = t + 256;
            Ws[lin >> 4][lin & 15] = wg[(size_t)(kb + (lin >> 4)) * RNK + (lin & 15)];
        }
        __syncthreads();
#pragma unroll
        for (int kk = 0; kk < 32; kk++) {
            float xv = xr[kb + kk];
#pragma unroll
            for (int u = 0; u < 8; u++) acc[u] += xv * Ws[kk][rh + u];
        }
    }
    if (valid) {
        float* dst = g_Ascr + (size_t)(row0 + row) * RNK + rh;
#pragma unroll
        for (int u = 0; u < 8; u++) dst[u] = SCALEF * acc[u];
    }
}

// ---------------- kernel 2: A tile images (hi/lo bf16, row-major) ----------------
__global__ __launch_bounds__(256) void prepA_kernel(const float* __restrict__ x) {
    int tile = blockIdx.x, ci = blockIdx.y;
    int rows = g_tile_rows[tile];
    if (rows == 0) return;
    int row0 = g_tile_row0[tile];
    int t = threadIdx.x;
    int kq = (t & 7) * 8;
    uint4* bh = gA_hi + ((size_t)tile * NCHUNK + ci) * CHUNK_U4;
    uint4* bl = gA_lo + ((size_t)tile * NCHUNK + ci) * CHUNK_U4;
#pragma unroll
    for (int it = 0; it < 4; it++) {
        int r = (t >> 3) + it * 32;
        float v[8];
        if (r < rows) {
            const float* p = x + (size_t)(row0 + r) * DIN + ci * KC + kq;
            float4 a = *(const float4*)p;
            float4 b = *(const float4*)(p + 4);
            v[0] = a.x; v[1] = a.y; v[2] = a.z; v[3] = a.w;
            v[4] = b.x; v[5] = b.y; v[6] = b.z; v[7] = b.w;
        } else {
#pragma unroll
            for (int j = 0; j < 8; j++) v[j] = 0.f;
        }
        write_img(bh, bl, r, kq, v);
    }
}

// ---------------- kernel 3: transpose W_base -> B images [n][k] ----------------
__global__ __launch_bounds__(256) void prepB_kernel(const float* __restrict__ Wb) {
    int bx = blockIdx.x;          // g*8 + ncb
    int ci = blockIdx.y;
    int g = bx >> 3, ncb = bx & 7;
    __shared__ float S[KC][129];
    int t = threadIdx.x;
    const float* W = Wb + (size_t)g * DIN * DOUT + (size_t)ci * KC * DOUT + ncb * BN;
    int c4 = (t & 31) * 4;
    int kr0 = t >> 5;
#pragma unroll
    for (int i = 0; i < 8; i++) {
        int kr = kr0 + i * 8;
        float4 v = *(const float4*)(W + (size_t)kr * DOUT + c4);
        S[kr][c4 + 0] = v.x; S[kr][c4 + 1] = v.y;
        S[kr][c4 + 2] = v.z; S[kr][c4 + 3] = v.w;
    }
    __syncthreads();
    int kq = (t & 7) * 8;
    uint4* bh = gB_hi + ((size_t)bx * NCHUNK + ci) * CHUNK_U4;
    uint4* bl = gB_lo + ((size_t)bx * NCHUNK + ci) * CHUNK_U4;
#pragma unroll
    for (int it = 0; it < 4; it++) {
        int r = (t >> 3) + it * 32;   // n-row
        float v[8];
#pragma unroll
        for (int j = 0; j < 8; j++) v[j] = S[kq + j][r];
        write_img(bh, bl, r, kq, v);
    }
}

// ---------------- kernel 4: LoRA chunk images (chunk 16, K padded 16->64) ----------------
__global__ __launch_bounds__(256) void prepL_kernel(const float* __restrict__ WBl) {
    int b = blockIdx.x;
    int t = threadIdx.x;
    int kq = (t & 7) * 8;
    if (b < MAX_TILES) {
        int rows = g_tile_rows[b];
        if (rows == 0) return;
        int row0 = g_tile_row0[b];
        uint4* bh = gA_hi + ((size_t)b * NCHUNK + 16) * CHUNK_U4;
        uint4* bl = gA_lo + ((size_t)b * NCHUNK + 16) * CHUNK_U4;
#pragma unroll
        for (int it = 0; it < 4; it++) {
            int r = (t >> 3) + it * 32;
            float v[8];
#pragma unroll
            for (int j = 0; j < 8; j++) {
                int k = kq + j;
                v[j] = (r < rows && k < RNK) ? g_Ascr[(size_t)(row0 + r) * RNK + k] : 0.f;
            }
            write_img(bh, bl, r, kq, v);
        }
    } else {
        int idx = b - MAX_TILES;      // 0..63 : g*8+ncb
        int g = idx >> 3, ncb = idx & 7;
        const float* w = WBl + (size_t)g * RNK * DOUT + ncb * BN;
        uint4* bh = gB_hi + ((size_t)idx * NCHUNK + 16) * CHUNK_U4;
        uint4* bl = gB_lo + ((size_t)idx * NCHUNK + 16) * CHUNK_U4;
#pragma unroll
        for (int it = 0; it < 4; it++) {
            int r = (t >> 3) + it * 32;   // n-row
            float v[8];
#pragma unroll
            for (int j = 0; j < 8; j++) {
                int k = kq + j;
                v[j] = (k < RNK) ? w[(size_t)k * DOUT + r] : 0.f;
            }
            write_img(bh, bl, r, kq, v);
        }
    }
}

// ---------------- kernel 5: bf16 hi/lo 3-pass mma.sync GEMM, fused LoRA ----------------
__global__ __launch_bounds__(256) void main_gemm(float* __restrict__ out) {
    int tile = blockIdx.x;
    int rows = g_tile_rows[tile];
    if (rows == 0) return;
    int row0 = g_tile_row0[tile];
    int grp  = g_tile_grp[tile];
    int ncb  = blockIdx.y;
    int col0 = ncb * BN;

    extern __shared__ char smem[];
    uint32_t sbase = smem_u32(smem);
    int t = threadIdx.x;
    int lane = t & 31, warp = t >> 5;
    int wm = warp & 3;        // m-quadrant: 0..3 -> m offset 32*wm
    int wn = warp >> 2;       // n-half:     0..1 -> n offset 64*wn

    const uint4* src0 = gA_hi + (size_t)tile * NCHUNK * CHUNK_U4;
    const uint4* src1 = gA_lo + (size_t)tile * NCHUNK * CHUNK_U4;
    const uint4* src2 = gB_hi + (size_t)(grp * 8 + ncb) * NCHUNK * CHUNK_U4;
    const uint4* src3 = gB_lo + (size_t)(grp * 8 + ncb) * NCHUNK * CHUNK_U4;

    float acc[2][8][4];
#pragma unroll
    for (int i = 0; i < 2; i++)
#pragma unroll
        for (int j = 0; j < 8; j++)
#pragma unroll
            for (int q = 0; q < 4; q++) acc[i][j][q] = 0.f;

    // ---- async-copy one chunk into stage s ----
    auto issue = [&](int ci, int s) {
        if (ci < NCHUNK) {
            uint32_t dst0 = sbase + (uint32_t)s * STAGE_B;
#pragma unroll
            for (int it = 0; it < 16; it++) {
                int lin = it * 256 + t;
                int mat = lin >> 10;
                int idx = lin & 1023;
                int row = idx >> 3, j = idx & 7;
                uint32_t d = dst0 + (uint32_t)mat * MAT_B + (uint32_t)row * ROWB + j * 16;
                const uint4* sp = (mat == 0) ? src0 : (mat == 1) ? src1 : (mat == 2) ? src2 : src3;
                CP_ASYNC16(d, sp + (size_t)ci * CHUNK_U4 + idx);
            }
        }
        CP_COMMIT();
    };

    issue(0, 0);
    issue(1, 1);

    // ldmatrix address components (per lane)
    int lr = lane & 15;           // row within 16-row tile
    int lko = (lane >> 4) * 16;   // +16B for k-offset-8 matrices

    for (int ci = 0; ci < NCHUNK; ci++) {
        int s = ci & 1;
        CP_WAIT1();
        __syncthreads();

        uint32_t stg = sbase + (uint32_t)s * STAGE_B;
#pragma unroll
        for (int ks = 0; ks < 4; ks++) {
            uint32_t kb = (uint32_t)ks * 32 + lko;
            // A fragments: [mtile i][h]
            uint32_t aF[2][2][4];
#pragma unroll
            for (int i = 0; i < 2; i++) {
                uint32_t rowa = (uint32_t)(wm * 32 + i * 16 + lr) * ROWB + kb;
                ldm_x4(aF[i][0], stg + 0 * MAT_B + rowa);
                ldm_x4(aF[i][1], stg + 1 * MAT_B + rowa);
            }
            // B fragments: [jp pair][h]; regs r0..r3 = (n0-7,k0-7),(n8-15,k0-7),(n0-7,k8+),(n8-15,k8+)
            uint32_t bF[4][2][4];
#pragma unroll
            for (int jp = 0; jp < 4; jp++) {
                uint32_t rowb = (uint32_t)(wn * 64 + jp * 16 + lr) * ROWB + kb;
                ldm_x4(bF[jp][0], stg + 2 * MAT_B + rowb);
                ldm_x4(bF[jp][1], stg + 3 * MAT_B + rowb);
            }
#pragma unroll
            for (int i = 0; i < 2; i++)
#pragma unroll
                for (int jp = 0; jp < 4; jp++)
#pragma unroll
                    for (int w2 = 0; w2 < 2; w2++) {
                        int j = jp * 2 + w2;
                        uint32_t bh0 = bF[jp][0][w2], bh1 = bF[jp][0][w2 + 2];
                        uint32_t bl0 = bF[jp][1][w2], bl1 = bF[jp][1][w2 + 2];
                        mma_bf16(acc[i][j], aF[i][0], bh0, bh1);  // hi*hi
                        mma_bf16(acc[i][j], aF[i][0], bl0, bl1);  // hi*lo
                        mma_bf16(acc[i][j], aF[i][1], bh0, bh1);  // lo*hi
                    }
        }
        __syncthreads();
        issue(ci + 2, s);
    }

    // ---- epilogue: direct stores (each element written exactly once) ----
    int lr4 = lane >> 2;
    int lc2 = 2 * (lane & 3);
#pragma unroll
    for (int i = 0; i < 2; i++) {
        int mloc0 = wm * 32 + i * 16 + lr4;
#pragma unroll
        for (int j = 0; j < 8; j++) {
            int c = col0 + wn * 64 + j * 8 + lc2;
            if (mloc0 < rows) {
                float2 v = make_float2(acc[i][j][0], acc[i][j][1]);
                *(float2*)(out + (size_t)(row0 + mloc0) * DOUT + c) = v;
            }
            if (mloc0 + 8 < rows) {
                float2 v = make_float2(acc[i][j][2], acc[i][j][3]);
                *(float2*)(out + (size_t)(row0 + mloc0 + 8) * DOUT + c) = v;
            }
        }
    }
}

// ---------------- launch ----------------
extern "C" void kernel_launch(void* const* d_in, const int* in_sizes, int n_in,
                              void* d_out, int out_size) {
    const float* x   = (const float*)d_in[0];
    const int*   xg  = (const int*)d_in[1];   // x_groups (int32, int64-hedged)
    const float* Wb  = (const float*)d_in[2]; // [G, DIN, DOUT]
    const float* WA  = (const float*)d_in[3]; // [G, DIN, R]
    const float* WBl = (const float*)d_in[4]; // [G, R, DOUT]
    float* out = (float*)d_out;

    int N = in_sizes[0] / DIN;
    int maxTiles = (N + BM - 1) / BM + GNUM;

    cudaFuncSetAttribute(main_gemm, cudaFuncAttributeMaxDynamicSharedMemorySize, SMEM_MAIN);

    setup_kernel<<<1, 256>>>(xg, N);
    lora_a_kernel<<<maxTiles, 256>>>(x, WA);
    dim3 ga(maxTiles, 16);
    prepA_kernel<<<ga, 256>>>(x);
    dim3 gb(GNUM * 8, 16);
    prepB_kernel<<<gb, 256>>>(Wb);
    prepL_kernel<<<maxTiles + GNUM * 8, 256>>>(WBl);
    dim3 gm(maxTiles, DOUT / BN);
    main_gemm<<<gm, 256, SMEM_MAIN>>>(out);
}

// round 8
// speedup vs baseline: 1.6719x; 1.1082x over previous
#include <cuda_runtime.h>
#include <cuda_bf16.h>
#include <cstdint>

#define GNUM 8
#define DIN 1024
#define DOUT 1024
#define RNK 16
#define SCALEF 2.0f

#define BM 128
#define BN 128
#define KC 64                 // bf16 K elements per chunk
#define NCHUNK 17             // 16 real K-chunks + 1 LoRA chunk
#define MAX_N 8192
#define MAX_TILES ((MAX_N / BM) + GNUM)   // 72
#define CHUNK_U4 1024         // one 128x64 bf16 matrix image, in uint4 (16KB)

// smem: per stage 4 dense matrices (A_hi, A_lo, B_hi, B_lo), 128 rows x 128B
#define MAT_B 16384
#define STAGE_B 65536
#define SMEM_MAIN (2 * STAGE_B)   // 128KB

// ---------------- device scratch (no allocations allowed) ----------------
__device__ int g_tile_row0[MAX_TILES];
__device__ int g_tile_rows[MAX_TILES];
__device__ int g_tile_grp[MAX_TILES];
__device__ __align__(16) float g_Ascr[MAX_N * RNK];
// A images: [tile][chunk][{hi,lo}] each CHUNK_U4; B images: [g*8+ncb][chunk][{hi,lo}]
__device__ uint4 gA[MAX_TILES * NCHUNK * 2 * CHUNK_U4];
__device__ uint4 gB[GNUM * 8 * NCHUNK * 2 * CHUNK_U4];

// ---------------- PTX helpers (baseline ISA only; no 'a'-features) ----------------
__device__ __forceinline__ uint32_t smem_u32(const void* p) {
    uint32_t a;
    asm("{ .reg .u64 t; cvta.to.shared.u64 t, %1; cvt.u32.u64 %0, t; }" : "=r"(a) : "l"(p));
    return a;
}
#define MBARRIER_INIT(a, c) \
    asm volatile("mbarrier.init.shared.b64 [%0], %1;" :: "r"((uint32_t)(a)), "r"((uint32_t)(c)) : "memory")
#define MBARRIER_EXPECT_TX(a, tx) \
    asm volatile("mbarrier.arrive.expect_tx.shared.b64 _, [%0], %1;" \
                 :: "r"((uint32_t)(a)), "r"((uint32_t)(tx)) : "memory")
#define MBARRIER_WAIT_PARITY(a, ph) do { \
    uint32_t _m = (uint32_t)(a); uint32_t _p = (uint32_t)(ph); uint32_t _d; \
    asm volatile("{\n\t.reg .pred p;\n\t" \
        "mbarrier.try_wait.parity.acquire.cta.shared::cta.b64 p, [%1], %2;\n\t" \
        "selp.b32 %0, 1, 0, p;\n\t}" : "=r"(_d) : "r"(_m), "r"(_p) : "memory"); \
    if (!_d) { \
        asm volatile("{\n\t.reg .pred P1;\n\t" \
            "WL_%=:\n\t" \
            "mbarrier.try_wait.parity.acquire.cta.shared::cta.b64 P1, [%0], %1, 0x989680;\n\t" \
            "@P1 bra.uni WD_%=;\n\tbra.uni WL_%=;\n\tWD_%=:\n\t}" \
            :: "r"(_m), "r"(_p) : "memory"); \
    } } while (0)
#define CP_BULK(dst, src, bytes, mb) \
    asm volatile("cp.async.bulk.shared::cluster.global.mbarrier::complete_tx::bytes " \
                 "[%0], [%1], %2, [%3];" \
                 :: "r"((uint32_t)(dst)), "l"(src), "r"((uint32_t)(bytes)), \
                    "r"((uint32_t)(mb)) : "memory")

__device__ __forceinline__ void ldm_x4(uint32_t* r, uint32_t addr) {
    asm volatile("ldmatrix.sync.aligned.m8n8.x4.shared.b16 {%0,%1,%2,%3}, [%4];"
                 : "=r"(r[0]), "=r"(r[1]), "=r"(r[2]), "=r"(r[3]) : "r"(addr));
}
__device__ __forceinline__ void mma_bf16(float* d, const uint32_t* a, uint32_t b0, uint32_t b1) {
    asm volatile("mma.sync.aligned.m16n8k16.row.col.f32.bf16.bf16.f32 "
                 "{%0,%1,%2,%3}, {%4,%5,%6,%7}, {%8,%9}, {%0,%1,%2,%3};"
                 : "+f"(d[0]), "+f"(d[1]), "+f"(d[2]), "+f"(d[3])
                 : "r"(a[0]), "r"(a[1]), "r"(a[2]), "r"(a[3]), "r"(b0), "r"(b1));
}

// ---------------- hi/lo bf16 split ----------------
__device__ __forceinline__ void hilo8(const float* v, uint4& hi, uint4& lo) {
    uint32_t h[4], l[4];
#pragma unroll
    for (int p = 0; p < 4; p++) {
        float a = v[2 * p], b = v[2 * p + 1];
        __nv_bfloat16 ha = __float2bfloat16(a), hb = __float2bfloat16(b);
        float ra = __bfloat162float(ha), rb = __bfloat162float(hb);
        __nv_bfloat16 la = __float2bfloat16(a - ra), lb = __float2bfloat16(b - rb);
        __nv_bfloat162 hp; hp.x = ha; hp.y = hb;
        __nv_bfloat162 lp; lp.x = la; lp.y = lb;
        h[p] = *reinterpret_cast<uint32_t*>(&hp);
        l[p] = *reinterpret_cast<uint32_t*>(&lp);
    }
    hi = make_uint4(h[0], h[1], h[2], h[3]);
    lo = make_uint4(l[0], l[1], l[2], l[3]);
}

// swizzled image write: dense 128B rows, 16B unit column XORed with (row&7)
__device__ __forceinline__ void write_img(uint4* base, int row, int kq, const float* v) {
    uint32_t s = (uint32_t)row * 8u + (((uint32_t)kq >> 3) ^ ((uint32_t)row & 7u));
    uint4 hi, lo;
    hilo8(v, hi, lo);
    base[s] = hi;
    base[CHUNK_U4 + s] = lo;
}

__device__ __forceinline__ int get_group(const int* p, int i, int is64) {
    return is64 ? p[2 * i] : p[i];
}

// ---------------- kernel 0: group boundaries + tile list ----------------
__global__ void setup_kernel(const int* __restrict__ gr, int N) {
    __shared__ int start[GNUM + 1];
    __shared__ int is64_s;
    int t = threadIdx.x;
    if (t == 0) {
        int wl = gr[N - 1], wp = gr[N - 2];
        is64_s = (wl == 0 && wp != 0) ? 1 : 0;
    }
    if (t < GNUM) start[t] = -1;
    if (t == GNUM) start[GNUM] = N;
    __syncthreads();
    int is64 = is64_s;
    int per = (N + 255) >> 8;
    int b = t * per, e = min(N, b + per);
    if (b < N) {
        int gp = (b == 0) ? -1 : get_group(gr, b - 1, is64);
        for (int i = b; i < e; i++) {
            int g = get_group(gr, i, is64);
            if (g != gp) {
                for (int gg = gp + 1; gg <= g; gg++) start[gg] = i;
                gp = g;
            }
        }
    }
    __syncthreads();
    if (t == 0) {
        for (int g = GNUM - 1; g >= 0; g--)
            if (start[g] < 0) start[g] = start[g + 1];
        int nt = 0;
        for (int g = 0; g < GNUM; g++) {
            int s = start[g], e2 = start[g + 1];
            for (int r0 = s; r0 < e2; r0 += BM) {
                g_tile_row0[nt] = r0;
                g_tile_rows[nt] = min(BM, e2 - r0);
                g_tile_grp[nt]  = g;
                nt++;
            }
        }
        for (int i = nt; i < MAX_TILES; i++) g_tile_rows[i] = 0;
    }
}

// ---------------- kernel 1: A_scaled = SCALE * (x @ W_A[g]) ----------------
__global__ __launch_bounds__(256) void lora_a_kernel(const float* __restrict__ x,
                                                     const float* __restrict__ WA) {
    int tile = blockIdx.x;
    int rows = g_tile_rows[tile];
    if (rows == 0) return;
    int row0 = g_tile_row0[tile];
    int grp  = g_tile_grp[tile];

    int t   = threadIdx.x;
    int row = t >> 1;
    int rh  = (t & 1) * 8;
    bool valid = row < rows;
    const float* xr = x + (size_t)(row0 + (valid ? row : 0)) * DIN;
    const float* wg = WA + (size_t)grp * DIN * RNK;

    __shared__ float Ws[32][RNK];
    float acc[8] = {0.f, 0.f, 0.f, 0.f, 0.f, 0.f, 0.f, 0.f};

    for (int kb = 0; kb < DIN; kb += 32) {
        __syncthreads();
        {
            int lin = t;
            Ws[lin >> 4][lin & 15] = wg[(size_t)(kb + (lin >> 4)) * RNK + (lin & 15)];
            lin = t + 256;
            Ws[lin >> 4][lin & 15] = wg[(size_t)(kb + (lin >> 4)) * RNK + (lin & 15)];
        }
        __syncthreads();
#pragma unroll
        for (int kk = 0; kk < 32; kk++) {
            float xv = xr[kb + kk];
#pragma unroll
            for (int u = 0; u < 8; u++) acc[u] += xv * Ws[kk][rh + u];
        }
    }
    if (valid) {
        float* dst = g_Ascr + (size_t)(row0 + row) * RNK + rh;
#pragma unroll
        for (int u = 0; u < 8; u++) dst[u] = SCALEF * acc[u];
    }
}

// ---------------- kernel 2: A tile images (hi/lo bf16, swizzled) ----------------
__global__ __launch_bounds__(256) void prepA_kernel(const float* __restrict__ x) {
    int tile = blockIdx.x, ci = blockIdx.y;
    int rows = g_tile_rows[tile];
    if (rows == 0) return;
    int row0 = g_tile_row0[tile];
    int t = threadIdx.x;
    int kq = (t & 7) * 8;
    uint4* base = gA + ((size_t)(tile * NCHUNK + ci)) * 2 * CHUNK_U4;
#pragma unroll
    for (int it = 0; it < 4; it++) {
        int r = (t >> 3) + it * 32;
        float v[8];
        if (r < rows) {
            const float* p = x + (size_t)(row0 + r) * DIN + ci * KC + kq;
            float4 a = *(const float4*)p;
            float4 b = *(const float4*)(p + 4);
            v[0] = a.x; v[1] = a.y; v[2] = a.z; v[3] = a.w;
            v[4] = b.x; v[5] = b.y; v[6] = b.z; v[7] = b.w;
        } else {
#pragma unroll
            for (int j = 0; j < 8; j++) v[j] = 0.f;
        }
        write_img(base, r, kq, v);
    }
}

// ---------------- kernel 3: transpose W_base -> B images [n][k] (swizzled) ----------------
__global__ __launch_bounds__(256) void prepB_kernel(const float* __restrict__ Wb) {
    int bx = blockIdx.x;          // g*8 + ncb
    int ci = blockIdx.y;
    int g = bx >> 3, ncb = bx & 7;
    __shared__ float S[KC][129];
    int t = threadIdx.x;
    const float* W = Wb + (size_t)g * DIN * DOUT + (size_t)ci * KC * DOUT + ncb * BN;
    int c4 = (t & 31) * 4;
    int kr0 = t >> 5;
#pragma unroll
    for (int i = 0; i < 8; i++) {
        int kr = kr0 + i * 8;
        float4 v = *(const float4*)(W + (size_t)kr * DOUT + c4);
        S[kr][c4 + 0] = v.x; S[kr][c4 + 1] = v.y;
        S[kr][c4 + 2] = v.z; S[kr][c4 + 3] = v.w;
    }
    __syncthreads();
    int kq = (t & 7) * 8;
    uint4* base = gB + ((size_t)(bx * NCHUNK + ci)) * 2 * CHUNK_U4;
#pragma unroll
    for (int it = 0; it < 4; it++) {
        int r = (t >> 3) + it * 32;   // n-row
        float v[8];
#pragma unroll
        for (int j = 0; j < 8; j++) v[j] = S[kq + j][r];
        write_img(base, r, kq, v);
    }
}

// ---------------- kernel 4: LoRA chunk images (chunk 16, K padded 16->64) ----------------
__global__ __launch_bounds__(256) void prepL_kernel(const float* __restrict__ WBl) {
    int b = blockIdx.x;
    int t = threadIdx.x;
    int kq = (t & 7) * 8;
    if (b < MAX_TILES) {
        int rows = g_tile_rows[b];
        if (rows == 0) return;
        int row0 = g_tile_row0[b];
        uint4* base = gA + ((size_t)(b * NCHUNK + 16)) * 2 * CHUNK_U4;
#pragma unroll
        for (int it = 0; it < 4; it++) {
            int r = (t >> 3) + it * 32;
            float v[8];
#pragma unroll
            for (int j = 0; j < 8; j++) {
                int k = kq + j;
                v[j] = (r < rows && k < RNK) ? g_Ascr[(size_t)(row0 + r) * RNK + k] : 0.f;
            }
            write_img(base, r, kq, v);
        }
    } else {
        int idx = b - MAX_TILES;      // 0..63 : g*8+ncb
        int g = idx >> 3, ncb = idx & 7;
        const float* w = WBl + (size_t)g * RNK * DOUT + ncb * BN;
        uint4* base = gB + ((size_t)(idx * NCHUNK + 16)) * 2 * CHUNK_U4;
#pragma unroll
        for (int it = 0; it < 4; it++) {
            int r = (t >> 3) + it * 32;   // n-row
            float v[8];
#pragma unroll
            for (int j = 0; j < 8; j++) {
                int k = kq + j;
                v[j] = (k < RNK) ? w[(size_t)k * DOUT + r] : 0.f;
            }
            write_img(base, r, kq, v);
        }
    }
}

// ---------------- kernel 5: bf16 hi/lo 3-pass mma.sync GEMM, bulk-copy pipeline ----------------
__global__ __launch_bounds__(256) void main_gemm(float* __restrict__ out) {
    int tile = blockIdx.x;
    int rows = g_tile_rows[tile];
    if (rows == 0) return;
    int row0 = g_tile_row0[tile];
    int grp  = g_tile_grp[tile];
    int ncb  = blockIdx.y;
    int col0 = ncb * BN;

    extern __shared__ char smem[];
    __shared__ __align__(16) uint64_t mbar[2];
    uint32_t sbase = smem_u32(smem);
    int t = threadIdx.x;
    int lane = t & 31, warp = t >> 5;
    int wm = warp & 3;        // m-quadrant
    int wn = warp >> 2;       // n-half

    uint32_t mbs[2] = {smem_u32(&mbar[0]), smem_u32(&mbar[1])};
    if (t == 0) {
        MBARRIER_INIT(mbs[0], 1);
        MBARRIER_INIT(mbs[1], 1);
    }
    __syncthreads();

    const uint4* srcA = gA + (size_t)tile * NCHUNK * 2 * CHUNK_U4;
    const uint4* srcB = gB + (size_t)(grp * 8 + ncb) * NCHUNK * 2 * CHUNK_U4;

    if (t == 0) {
        MBARRIER_EXPECT_TX(mbs[0], STAGE_B);
        CP_BULK(sbase,          (const void*)srcA,          32768, mbs[0]);
        CP_BULK(sbase + 32768,  (const void*)srcB,          32768, mbs[0]);
        MBARRIER_EXPECT_TX(mbs[1], STAGE_B);
        CP_BULK(sbase + STAGE_B,         (const void*)(srcA + 2 * CHUNK_U4), 32768, mbs[1]);
        CP_BULK(sbase + STAGE_B + 32768, (const void*)(srcB + 2 * CHUNK_U4), 32768, mbs[1]);
    }

    // per-thread fragment address components (swizzled layout)
    int lr = lane & 15;
    int hf = lane >> 4;       // +8 k-elements half
    uint32_t rowA[2], swA[2], rowB[4], swB[4];
#pragma unroll
    for (int i = 0; i < 2; i++) {
        int rr = wm * 32 + i * 16 + lr;
        rowA[i] = (uint32_t)rr * 128u;
        swA[i]  = (uint32_t)(rr & 7);
    }
#pragma unroll
    for (int jp = 0; jp < 4; jp++) {
        int rr = wn * 64 + jp * 16 + lr;
        rowB[jp] = (uint32_t)rr * 128u;
        swB[jp]  = (uint32_t)(rr & 7);
    }

    float acc[2][8][4];
#pragma unroll
    for (int i = 0; i < 2; i++)
#pragma unroll
        for (int j = 0; j < 8; j++)
#pragma unroll
            for (int q = 0; q < 4; q++) acc[i][j][q] = 0.f;

    for (int ci = 0; ci < NCHUNK; ci++) {
        int s = ci & 1;
        MBARRIER_WAIT_PARITY(mbs[s], (ci >> 1) & 1);

        uint32_t stg = sbase + (uint32_t)s * STAGE_B;
#pragma unroll
        for (int ks = 0; ks < 4; ks++) {
            uint32_t u = (uint32_t)(ks * 2 + hf);
            uint32_t aF[2][2][4];
#pragma unroll
            for (int i = 0; i < 2; i++) {
                uint32_t a = stg + rowA[i] + ((u ^ swA[i]) << 4);
                ldm_x4(aF[i][0], a);              // A_hi
                ldm_x4(aF[i][1], a + MAT_B);      // A_lo
            }
            uint32_t bF[4][2][4];
#pragma unroll
            for (int jp = 0; jp < 4; jp++) {
                uint32_t a = stg + 2 * MAT_B + rowB[jp] + ((u ^ swB[jp]) << 4);
                ldm_x4(bF[jp][0], a);             // B_hi
                ldm_x4(bF[jp][1], a + MAT_B);     // B_lo
            }
#pragma unroll
            for (int i = 0; i < 2; i++)
#pragma unroll
                for (int jp = 0; jp < 4; jp++)
#pragma unroll
                    for (int w2 = 0; w2 < 2; w2++) {
                        int j = jp * 2 + w2;
                        uint32_t bh0 = bF[jp][0][w2], bh1 = bF[jp][0][w2 + 2];
                        uint32_t bl0 = bF[jp][1][w2], bl1 = bF[jp][1][w2 + 2];
                        mma_bf16(acc[i][j], aF[i][0], bh0, bh1);  // hi*hi
                        mma_bf16(acc[i][j], aF[i][0], bl0, bl1);  // hi*lo
                        mma_bf16(acc[i][j], aF[i][1], bh0, bh1);  // lo*hi
                    }
        }
        __syncthreads();
        if (t == 0 && ci + 2 < NCHUNK) {
            MBARRIER_EXPECT_TX(mbs[s], STAGE_B);
            CP_BULK(stg,         (const void*)(srcA + (size_t)(ci + 2) * 2 * CHUNK_U4),
                    32768, mbs[s]);
            CP_BULK(stg + 32768, (const void*)(srcB + (size_t)(ci + 2) * 2 * CHUNK_U4),
                    32768, mbs[s]);
        }
    }

    // ---- epilogue: direct stores (each element written exactly once) ----
    int lr4 = lane >> 2;
    int lc2 = 2 * (lane & 3);
#pragma unroll
    for (int i = 0; i < 2; i++) {
        int mloc0 = wm * 32 + i * 16 + lr4;
#pragma unroll
        for (int j = 0; j < 8; j++) {
            int c = col0 + wn * 64 + j * 8 + lc2;
            if (mloc0 < rows) {
                float2 v = make_float2(acc[i][j][0], acc[i][j][1]);
                *(float2*)(out + (size_t)(row0 + mloc0) * DOUT + c) = v;
            }
            if (mloc0 + 8 < rows) {
                float2 v = make_float2(acc[i][j][2], acc[i][j][3]);
                *(float2*)(out + (size_t)(row0 + mloc0 + 8) * DOUT + c) = v;
            }
        }
    }
}

// ---------------- launch ----------------
extern "C" void kernel_launch(void* const* d_in, const int* in_sizes, int n_in,
                              void* d_out, int out_size) {
    const float* x   = (const float*)d_in[0];
    const int*   xg  = (const int*)d_in[1];   // x_groups (int32, int64-hedged)
    const float* Wb  = (const float*)d_in[2]; // [G, DIN, DOUT]
    const float* WA  = (const float*)d_in[3]; // [G, DIN, R]
    const float* WBl = (const float*)d_in[4]; // [G, R, DOUT]
    float* out = (float*)d_out;

    int N = in_sizes[0] / DIN;
    int maxTiles = (N + BM - 1) / BM + GNUM;

    cudaFuncSetAttribute(main_gemm, cudaFuncAttributeMaxDynamicSharedMemorySize, SMEM_MAIN);

    setup_kernel<<<1, 256>>>(xg, N);
    lora_a_kernel<<<maxTiles, 256>>>(x, WA);
    dim3 ga(maxTiles, 16);
    prepA_kernel<<<ga, 256>>>(x);
    dim3 gb(GNUM * 8, 16);
    prepB_kernel<<<gb, 256>>>(Wb);
    prepL_kernel<<<maxTiles + GNUM * 8, 256>>>(WBl);
    dim3 gm(maxTiles, DOUT / BN);
    main_gemm<<<gm, 256, SMEM_MAIN>>>(out);
}

// round 9
// speedup vs baseline: 1.7798x; 1.0645x over previous
#include <cuda_runtime.h>
#include <cuda_bf16.h>
#include <cstdint>

#define GNUM 8
#define DIN 1024
#define DOUT 1024
#define RNK 16
#define SCALEF 2.0f

#define BM 128
#define BN 128
#define KC 64                 // K elements per chunk
#define NCHUNK 17             // 16 real K-chunks + 1 LoRA chunk (K=16)
#define MAX_N 8192
#define MAX_TILES ((MAX_N / BM) + GNUM)   // 72

// A chunk image: 128 rows x 68-float pitch (64 used)  -> 34816 B
// B chunk image: 64 k-rows x 132-float pitch (128 used) -> 33792 B
#define APITCH 68
#define BPITCH 132
#define A_BYTES (128 * APITCH * 4)     // 34816
#define B_BYTES (64 * BPITCH * 4)      // 33792
#define A_U4 (A_BYTES / 16)            // 2176
#define B_U4 (B_BYTES / 16)            // 2112
#define STAGE_B (A_BYTES + B_BYTES)    // 68608
#define SMEM_MAIN (2 * STAGE_B)        // 137216

// ---------------- device scratch (no allocations allowed) ----------------
__device__ int g_tile_row0[MAX_TILES];
__device__ int g_tile_rows[MAX_TILES];
__device__ int g_tile_grp[MAX_TILES];
__device__ __align__(16) float g_Ascr[MAX_N * RNK];
__device__ uint4 gA[MAX_TILES * NCHUNK * A_U4];   // tf32 A images
__device__ uint4 gB[GNUM * 8 * NCHUNK * B_U4];    // tf32 B images

// ---------------- PTX helpers (baseline ISA only; no 'a'-features) ----------------
__device__ __forceinline__ uint32_t smem_u32(const void* p) {
    uint32_t a;
    asm("{ .reg .u64 t; cvta.to.shared.u64 t, %1; cvt.u32.u64 %0, t; }" : "=r"(a) : "l"(p));
    return a;
}
#define MBARRIER_INIT(a, c) \
    asm volatile("mbarrier.init.shared.b64 [%0], %1;" :: "r"((uint32_t)(a)), "r"((uint32_t)(c)) : "memory")
#define MBARRIER_EXPECT_TX(a, tx) \
    asm volatile("mbarrier.arrive.expect_tx.shared.b64 _, [%0], %1;" \
                 :: "r"((uint32_t)(a)), "r"((uint32_t)(tx)) : "memory")
#define MBARRIER_WAIT_PARITY(a, ph) do { \
    uint32_t _m = (uint32_t)(a); uint32_t _p = (uint32_t)(ph); uint32_t _d; \
    asm volatile("{\n\t.reg .pred p;\n\t" \
        "mbarrier.try_wait.parity.acquire.cta.shared::cta.b64 p, [%1], %2;\n\t" \
        "selp.b32 %0, 1, 0, p;\n\t}" : "=r"(_d) : "r"(_m), "r"(_p) : "memory"); \
    if (!_d) { \
        asm volatile("{\n\t.reg .pred P1;\n\t" \
            "WL_%=:\n\t" \
            "mbarrier.try_wait.parity.acquire.cta.shared::cta.b64 P1, [%0], %1, 0x989680;\n\t" \
            "@P1 bra.uni WD_%=;\n\tbra.uni WL_%=;\n\tWD_%=:\n\t}" \
            :: "r"(_m), "r"(_p) : "memory"); \
    } } while (0)
#define CP_BULK(dst, src, bytes, mb) \
    asm volatile("cp.async.bulk.shared::cluster.global.mbarrier::complete_tx::bytes " \
                 "[%0], [%1], %2, [%3];" \
                 :: "r"((uint32_t)(dst)), "l"(src), "r"((uint32_t)(bytes)), \
                    "r"((uint32_t)(mb)) : "memory")

__device__ __forceinline__ float to_tf32(float x) {
    float r;
    asm("cvt.rna.tf32.f32 %0, %1;" : "=f"(r) : "f"(x));
    return r;
}
__device__ __forceinline__ void mma_tf32(float* d, const uint32_t* a, uint32_t b0, uint32_t b1) {
    asm volatile("mma.sync.aligned.m16n8k8.row.col.f32.tf32.tf32.f32 "
                 "{%0,%1,%2,%3}, {%4,%5,%6,%7}, {%8,%9}, {%0,%1,%2,%3};"
                 : "+f"(d[0]), "+f"(d[1]), "+f"(d[2]), "+f"(d[3])
                 : "r"(a[0]), "r"(a[1]), "r"(a[2]), "r"(a[3]), "r"(b0), "r"(b1));
}

__device__ __forceinline__ int get_group(const int* p, int i, int is64) {
    return is64 ? p[2 * i] : p[i];
}

// ---------------- kernel 0: group boundaries + tile list ----------------
__global__ void setup_kernel(const int* __restrict__ gr, int N) {
    __shared__ int start[GNUM + 1];
    __shared__ int is64_s;
    int t = threadIdx.x;
    if (t == 0) {
        int wl = gr[N - 1], wp = gr[N - 2];
        is64_s = (wl == 0 && wp != 0) ? 1 : 0;
    }
    if (t < GNUM) start[t] = -1;
    if (t == GNUM) start[GNUM] = N;
    __syncthreads();
    int is64 = is64_s;
    int per = (N + 255) >> 8;
    int b = t * per, e = min(N, b + per);
    if (b < N) {
        int gp = (b == 0) ? -1 : get_group(gr, b - 1, is64);
        for (int i = b; i < e; i++) {
            int g = get_group(gr, i, is64);
            if (g != gp) {
                for (int gg = gp + 1; gg <= g; gg++) start[gg] = i;
                gp = g;
            }
        }
    }
    __syncthreads();
    if (t == 0) {
        for (int g = GNUM - 1; g >= 0; g--)
            if (start[g] < 0) start[g] = start[g + 1];
        int nt = 0;
        for (int g = 0; g < GNUM; g++) {
            int s = start[g], e2 = start[g + 1];
            for (int r0 = s; r0 < e2; r0 += BM) {
                g_tile_row0[nt] = r0;
                g_tile_rows[nt] = min(BM, e2 - r0);
                g_tile_grp[nt]  = g;
                nt++;
            }
        }
        for (int i = nt; i < MAX_TILES; i++) g_tile_rows[i] = 0;
    }
}

// ---------------- kernel 1: A_scaled = SCALE * (x @ W_A[g]) ----------------
__global__ __launch_bounds__(256) void lora_a_kernel(const float* __restrict__ x,
                                                     const float* __restrict__ WA) {
    int tile = blockIdx.x;
    int rows = g_tile_rows[tile];
    if (rows == 0) return;
    int row0 = g_tile_row0[tile];
    int grp  = g_tile_grp[tile];

    int t   = threadIdx.x;
    int row = t >> 1;
    int rh  = (t & 1) * 8;
    bool valid = row < rows;
    const float* xr = x + (size_t)(row0 + (valid ? row : 0)) * DIN;
    const float* wg = WA + (size_t)grp * DIN * RNK;

    __shared__ float Ws[32][RNK];
    float acc[8] = {0.f, 0.f, 0.f, 0.f, 0.f, 0.f, 0.f, 0.f};

    for (int kb = 0; kb < DIN; kb += 32) {
        __syncthreads();
        {
            int lin = t;
            Ws[lin >> 4][lin & 15] = wg[(size_t)(kb + (lin >> 4)) * RNK + (lin & 15)];
            lin = t + 256;
            Ws[lin >> 4][lin & 15] = wg[(size_t)(kb + (lin >> 4)) * RNK + (lin & 15)];
        }
        __syncthreads();
#pragma unroll
        for (int kk = 0; kk < 32; kk++) {
            float xv = xr[kb + kk];
#pragma unroll
            for (int u = 0; u < 8; u++) acc[u] += xv * Ws[kk][rh + u];
        }
    }
    if (valid) {
        float* dst = g_Ascr + (size_t)(row0 + row) * RNK + rh;
#pragma unroll
        for (int u = 0; u < 8; u++) dst[u] = SCALEF * acc[u];
    }
}

// ---------------- kernel 2: A tile images (tf32, pitch 68) ----------------
__global__ __launch_bounds__(256) void prepA_kernel(const float* __restrict__ x) {
    int tile = blockIdx.x, ci = blockIdx.y;
    int rows = g_tile_rows[tile];
    if (rows == 0) return;
    int row0 = g_tile_row0[tile];
    int t = threadIdx.x;
    int m  = t >> 1;
    int k0 = (t & 1) * 32;
    float* dst = (float*)(gA + ((size_t)tile * NCHUNK + ci) * A_U4) + m * APITCH + k0;
    if (m < rows) {
        const float* src = x + (size_t)(row0 + m) * DIN + ci * KC + k0;
#pragma unroll
        for (int kk = 0; kk < 32; kk += 4) {
            float4 v = *(const float4*)(src + kk);
            v.x = to_tf32(v.x); v.y = to_tf32(v.y);
            v.z = to_tf32(v.z); v.w = to_tf32(v.w);
            *(float4*)(dst + kk) = v;
        }
    } else {
        float4 z = make_float4(0.f, 0.f, 0.f, 0.f);
#pragma unroll
        for (int kk = 0; kk < 32; kk += 4) *(float4*)(dst + kk) = z;
    }
}

// ---------------- kernel 3: B images (tf32, [k][n], pitch 132, no transpose) --------
__global__ __launch_bounds__(256) void prepB_kernel(const float* __restrict__ Wb) {
    int bx = blockIdx.x;          // g*8 + ncb
    int ci = blockIdx.y;
    int g = bx >> 3, ncb = bx & 7;
    int t = threadIdx.x;
    int k  = t >> 2;
    int nq = (t & 3) * 32;
    const float* src = Wb + ((size_t)g * DIN + ci * KC + k) * DOUT + ncb * BN + nq;
    float* dst = (float*)(gB + ((size_t)bx * NCHUNK + ci) * B_U4) + k * BPITCH + nq;
#pragma unroll
    for (int nn = 0; nn < 32; nn += 4) {
        float4 v = *(const float4*)(src + nn);
        v.x = to_tf32(v.x); v.y = to_tf32(v.y);
        v.z = to_tf32(v.z); v.w = to_tf32(v.w);
        *(float4*)(dst + nn) = v;
    }
}

// ---------------- kernel 4: LoRA chunk images (chunk 16, K=16) ----------------
__global__ __launch_bounds__(256) void prepL_kernel(const float* __restrict__ WBl) {
    int b = blockIdx.x;
    int t = threadIdx.x;
    if (b < MAX_TILES) {
        int rows = g_tile_rows[b];
        if (rows == 0) return;
        int row0 = g_tile_row0[b];
        if (t < 128) {
            float* dst = (float*)(gA + ((size_t)b * NCHUNK + 16) * A_U4) + t * APITCH;
            if (t < rows) {
                const float* src = g_Ascr + (size_t)(row0 + t) * RNK;
#pragma unroll
                for (int kk = 0; kk < RNK; kk += 4) {
                    float4 v = *(const float4*)(src + kk);
                    v.x = to_tf32(v.x); v.y = to_tf32(v.y);
                    v.z = to_tf32(v.z); v.w = to_tf32(v.w);
                    *(float4*)(dst + kk) = v;
                }
            } else {
                float4 z = make_float4(0.f, 0.f, 0.f, 0.f);
#pragma unroll
                for (int kk = 0; kk < RNK; kk += 4) *(float4*)(dst + kk) = z;
            }
        }
    } else {
        int idx = b - MAX_TILES;      // 0..63 : g*8+ncb
        int g = idx >> 3, ncb = idx & 7;
        int k  = t >> 4;              // 0..15
        int nq = (t & 15) * 8;
        const float* src = WBl + ((size_t)g * RNK + k) * DOUT + ncb * BN + nq;
        float* dst = (float*)(gB + ((size_t)idx * NCHUNK + 16) * B_U4) + k * BPITCH + nq;
#pragma unroll
        for (int nn = 0; nn < 8; nn += 4) {
            float4 v = *(const float4*)(src + nn);
            v.x = to_tf32(v.x); v.y = to_tf32(v.y);
            v.z = to_tf32(v.z); v.w = to_tf32(v.w);
            *(float4*)(dst + nn) = v;
        }
    }
}

// ---------------- kernel 5: 1-pass tf32 mma.sync GEMM, bulk-copy pipeline -------
__global__ __launch_bounds__(256) void main_gemm(float* __restrict__ out) {
    int tile = blockIdx.x;
    int rows = g_tile_rows[tile];
    if (rows == 0) return;
    int row0 = g_tile_row0[tile];
    int grp  = g_tile_grp[tile];
    int ncb  = blockIdx.y;
    int col0 = ncb * BN;

    extern __shared__ char smem[];
    __shared__ __align__(16) uint64_t mbar[2];
    uint32_t sbase = smem_u32(smem);
    int t = threadIdx.x;
    int lane = t & 31, warp = t >> 5;
    int wm = warp & 3;        // m-quadrant
    int wn = warp >> 2;       // n-half
    int g4 = lane >> 2, tig = lane & 3;

    uint32_t mbs[2] = {smem_u32(&mbar[0]), smem_u32(&mbar[1])};
    if (t == 0) {
        MBARRIER_INIT(mbs[0], 1);
        MBARRIER_INIT(mbs[1], 1);
    }
    __syncthreads();

    const uint4* srcA = gA + (size_t)tile * NCHUNK * A_U4;
    const uint4* srcB = gB + (size_t)(grp * 8 + ncb) * NCHUNK * B_U4;

    if (t == 0) {
        MBARRIER_EXPECT_TX(mbs[0], STAGE_B);
        CP_BULK(sbase,           (const void*)srcA,          A_BYTES, mbs[0]);
        CP_BULK(sbase + A_BYTES, (const void*)srcB,          B_BYTES, mbs[0]);
        MBARRIER_EXPECT_TX(mbs[1], STAGE_B);
        CP_BULK(sbase + STAGE_B,           (const void*)(srcA + A_U4), A_BYTES, mbs[1]);
        CP_BULK(sbase + STAGE_B + A_BYTES, (const void*)(srcB + B_U4), B_BYTES, mbs[1]);
    }

    // per-thread invariant word offsets
    int baseA0 = (wm * 32 + g4) * APITCH + tig;         // i=0; i=1 adds 16*APITCH
    int baseB0 = tig * BPITCH + wn * 64 + g4;           // j adds 8; k-step adds 8*BPITCH

    float acc[2][8][4];
#pragma unroll
    for (int i = 0; i < 2; i++)
#pragma unroll
        for (int j = 0; j < 8; j++)
#pragma unroll
            for (int q = 0; q < 4; q++) acc[i][j][q] = 0.f;

    for (int ci = 0; ci < NCHUNK; ci++) {
        int s = ci & 1;
        MBARRIER_WAIT_PARITY(mbs[s], (ci >> 1) & 1);

        const uint32_t* SA = (const uint32_t*)(smem + s * STAGE_B);
        const uint32_t* SB = (const uint32_t*)(smem + s * STAGE_B + A_BYTES);
        int ksteps = (ci == NCHUNK - 1) ? 2 : 8;

        for (int ks = 0; ks < ksteps; ks++) {
            int kq = ks * 8;
            uint32_t a[2][4];
#pragma unroll
            for (int i = 0; i < 2; i++) {
                const uint32_t* pa = SA + baseA0 + i * 16 * APITCH + kq;
                a[i][0] = pa[0];
                a[i][1] = pa[8 * APITCH];
                a[i][2] = pa[4];
                a[i][3] = pa[8 * APITCH + 4];
            }
            uint32_t bfr[8][2];
            const uint32_t* pb = SB + baseB0 + kq * BPITCH;
#pragma unroll
            for (int j = 0; j < 8; j++) {
                bfr[j][0] = pb[j * 8];
                bfr[j][1] = pb[4 * BPITCH + j * 8];
            }
#pragma unroll
            for (int i = 0; i < 2; i++)
#pragma unroll
                for (int j = 0; j < 8; j++)
                    mma_tf32(acc[i][j], a[i], bfr[j][0], bfr[j][1]);
        }
        __syncthreads();
        if (t == 0 && ci + 2 < NCHUNK) {
            uint32_t stg = sbase + (uint32_t)s * STAGE_B;
            MBARRIER_EXPECT_TX(mbs[s], STAGE_B);
            CP_BULK(stg,           (const void*)(srcA + (size_t)(ci + 2) * A_U4), A_BYTES, mbs[s]);
            CP_BULK(stg + A_BYTES, (const void*)(srcB + (size_t)(ci + 2) * B_U4), B_BYTES, mbs[s]);
        }
    }

    // ---- epilogue: direct stores (each element written exactly once) ----
    int lr4 = lane >> 2;
    int lc2 = 2 * (lane & 3);
#pragma unroll
    for (int i = 0; i < 2; i++) {
        int mloc0 = wm * 32 + i * 16 + lr4;
#pragma unroll
        for (int j = 0; j < 8; j++) {
            int c = col0 + wn * 64 + j * 8 + lc2;
            if (mloc0 < rows) {
                float2 v = make_float2(acc[i][j][0], acc[i][j][1]);
                *(float2*)(out + (size_t)(row0 + mloc0) * DOUT + c) = v;
            }
            if (mloc0 + 8 < rows) {
                float2 v = make_float2(acc[i][j][2], acc[i][j][3]);
                *(float2*)(out + (size_t)(row0 + mloc0 + 8) * DOUT + c) = v;
            }
        }
    }
}

// ---------------- launch ----------------
extern "C" void kernel_launch(void* const* d_in, const int* in_sizes, int n_in,
                              void* d_out, int out_size) {
    const float* x   = (const float*)d_in[0];
    const int*   xg  = (const int*)d_in[1];   // x_groups (int32, int64-hedged)
    const float* Wb  = (const float*)d_in[2]; // [G, DIN, DOUT]
    const float* WA  = (const float*)d_in[3]; // [G, DIN, R]
    const float* WBl = (const float*)d_in[4]; // [G, R, DOUT]
    float* out = (float*)d_out;

    int N = in_sizes[0] / DIN;
    int maxTiles = (N + BM - 1) / BM + GNUM;

    cudaFuncSetAttribute(main_gemm, cudaFuncAttributeMaxDynamicSharedMemorySize, SMEM_MAIN);

    setup_kernel<<<1, 256>>>(xg, N);
    lora_a_kernel<<<maxTiles, 256>>>(x, WA);
    dim3 ga(maxTiles, 16);
    prepA_kernel<<<ga, 256>>>(x);
    dim3 gb(GNUM * 8, 16);
    prepB_kernel<<<gb, 256>>>(Wb);
    prepL_kernel<<<maxTiles + GNUM * 8, 256>>>(WBl);
    dim3 gm(maxTiles, DOUT / BN);
    main_gemm<<<gm, 256, SMEM_MAIN>>>(out);
}

// round 10
// speedup vs baseline: 2.7235x; 1.5302x over previous
#include <cuda_runtime.h>
#include <cuda_fp16.h>
#include <cstdint>

#define GNUM 8
#define DIN 1024
#define DOUT 1024
#define RNK 16
#define SCALEF 2.0f

#define BM 128
#define BN 128
#define KC 64                 // K elements per chunk
#define NCHUNK 17             // 16 real K-chunks + 1 LoRA chunk (K=16, 1 kstep)
#define MAX_N 8192
#define MAX_TILES ((MAX_N / BM) + GNUM)   // 72
#define CHUNK_U4 1024         // one 128x64 fp16 matrix image (16KB), in uint4

#define MAT_B 16384
#define STAGE_B 32768         // A image + B image
#define SMEM_MAIN (2 * STAGE_B)   // 64KB -> 2 CTAs/SM

// ---------------- device scratch (no allocations allowed) ----------------
__device__ int g_tile_row0[MAX_TILES];
__device__ int g_tile_rows[MAX_TILES];
__device__ int g_tile_grp[MAX_TILES];
__device__ __align__(16) float g_Ascr[MAX_N * RNK];
__device__ uint4 gA[MAX_TILES * NCHUNK * CHUNK_U4];   // fp16 A images [m][k]
__device__ uint4 gB[GNUM * 8 * NCHUNK * CHUNK_U4];    // fp16 B images [n][k]

// ---------------- PTX helpers (baseline ISA only; no 'a'-features) ----------------
__device__ __forceinline__ uint32_t smem_u32(const void* p) {
    uint32_t a;
    asm("{ .reg .u64 t; cvta.to.shared.u64 t, %1; cvt.u32.u64 %0, t; }" : "=r"(a) : "l"(p));
    return a;
}
#define MBARRIER_INIT(a, c) \
    asm volatile("mbarrier.init.shared.b64 [%0], %1;" :: "r"((uint32_t)(a)), "r"((uint32_t)(c)) : "memory")
#define MBARRIER_EXPECT_TX(a, tx) \
    asm volatile("mbarrier.arrive.expect_tx.shared.b64 _, [%0], %1;" \
                 :: "r"((uint32_t)(a)), "r"((uint32_t)(tx)) : "memory")
#define MBARRIER_WAIT_PARITY(a, ph) do { \
    uint32_t _m = (uint32_t)(a); uint32_t _p = (uint32_t)(ph); uint32_t _d; \
    asm volatile("{\n\t.reg .pred p;\n\t" \
        "mbarrier.try_wait.parity.acquire.cta.shared::cta.b64 p, [%1], %2;\n\t" \
        "selp.b32 %0, 1, 0, p;\n\t}" : "=r"(_d) : "r"(_m), "r"(_p) : "memory"); \
    if (!_d) { \
        asm volatile("{\n\t.reg .pred P1;\n\t" \
            "WL_%=:\n\t" \
            "mbarrier.try_wait.parity.acquire.cta.shared::cta.b64 P1, [%0], %1, 0x989680;\n\t" \
            "@P1 bra.uni WD_%=;\n\tbra.uni WL_%=;\n\tWD_%=:\n\t}" \
            :: "r"(_m), "r"(_p) : "memory"); \
    } } while (0)
#define CP_BULK(dst, src, bytes, mb) \
    asm volatile("cp.async.bulk.shared::cluster.global.mbarrier::complete_tx::bytes " \
                 "[%0], [%1], %2, [%3];" \
                 :: "r"((uint32_t)(dst)), "l"(src), "r"((uint32_t)(bytes)), \
                    "r"((uint32_t)(mb)) : "memory")

__device__ __forceinline__ void ldm_x4(uint32_t* r, uint32_t addr) {
    asm volatile("ldmatrix.sync.aligned.m8n8.x4.shared.b16 {%0,%1,%2,%3}, [%4];"
                 : "=r"(r[0]), "=r"(r[1]), "=r"(r[2]), "=r"(r[3]) : "r"(addr));
}
__device__ __forceinline__ void mma_f16(float* d, const uint32_t* a, uint32_t b0, uint32_t b1) {
    asm volatile("mma.sync.aligned.m16n8k16.row.col.f32.f16.f16.f32 "
                 "{%0,%1,%2,%3}, {%4,%5,%6,%7}, {%8,%9}, {%0,%1,%2,%3};"
                 : "+f"(d[0]), "+f"(d[1]), "+f"(d[2]), "+f"(d[3])
                 : "r"(a[0]), "r"(a[1]), "r"(a[2]), "r"(a[3]), "r"(b0), "r"(b1));
}

// ---------------- fp16 pack ----------------
__device__ __forceinline__ uint4 pack8h(const float* v) {
    uint32_t h[4];
#pragma unroll
    for (int p = 0; p < 4; p++) {
        __half2 hp = __floats2half2_rn(v[2 * p], v[2 * p + 1]);
        h[p] = *reinterpret_cast<uint32_t*>(&hp);
    }
    return make_uint4(h[0], h[1], h[2], h[3]);
}

// swizzled image write: dense 128B rows, 16B unit column XORed with (row&7)
__device__ __forceinline__ void write_img(uint4* base, int row, int kq, const float* v) {
    uint32_t s = (uint32_t)row * 8u + (((uint32_t)kq >> 3) ^ ((uint32_t)row & 7u));
    base[s] = pack8h(v);
}

__device__ __forceinline__ int get_group(const int* p, int i, int is64) {
    return is64 ? p[2 * i] : p[i];
}

// ---------------- kernel 0: group boundaries + tile list ----------------
__global__ void setup_kernel(const int* __restrict__ gr, int N) {
    __shared__ int start[GNUM + 1];
    __shared__ int is64_s;
    int t = threadIdx.x;
    if (t == 0) {
        int wl = gr[N - 1], wp = gr[N - 2];
        is64_s = (wl == 0 && wp != 0) ? 1 : 0;
    }
    if (t < GNUM) start[t] = -1;
    if (t == GNUM) start[GNUM] = N;
    __syncthreads();
    int is64 = is64_s;
    int per = (N + 255) >> 8;
    int b = t * per, e = min(N, b + per);
    if (b < N) {
        int gp = (b == 0) ? -1 : get_group(gr, b - 1, is64);
        for (int i = b; i < e; i++) {
            int g = get_group(gr, i, is64);
            if (g != gp) {
                for (int gg = gp + 1; gg <= g; gg++) start[gg] = i;
                gp = g;
            }
        }
    }
    __syncthreads();
    if (t == 0) {
        for (int g = GNUM - 1; g >= 0; g--)
            if (start[g] < 0) start[g] = start[g + 1];
        int nt = 0;
        for (int g = 0; g < GNUM; g++) {
            int s = start[g], e2 = start[g + 1];
            for (int r0 = s; r0 < e2; r0 += BM) {
                g_tile_row0[nt] = r0;
                g_tile_rows[nt] = min(BM, e2 - r0);
                g_tile_grp[nt]  = g;
                nt++;
            }
        }
        for (int i = nt; i < MAX_TILES; i++) g_tile_rows[i] = 0;
    }
}

// ---------------- kernel 1: A_scaled = SCALE * (x @ W_A[g]) ----------------
__global__ __launch_bounds__(256) void lora_a_kernel(const float* __restrict__ x,
                                                     const float* __restrict__ WA) {
    int tile = blockIdx.x;
    int rows = g_tile_rows[tile];
    if (rows == 0) return;
    int row0 = g_tile_row0[tile];
    int grp  = g_tile_grp[tile];

    int t   = threadIdx.x;
    int row = t >> 1;
    int rh  = (t & 1) * 8;
    bool valid = row < rows;
    const float* xr = x + (size_t)(row0 + (valid ? row : 0)) * DIN;
    const float* wg = WA + (size_t)grp * DIN * RNK;

    __shared__ float Ws[32][RNK];
    float acc[8] = {0.f, 0.f, 0.f, 0.f, 0.f, 0.f, 0.f, 0.f};

    for (int kb = 0; kb < DIN; kb += 32) {
        __syncthreads();
        {
            int lin = t;
            Ws[lin >> 4][lin & 15] = wg[(size_t)(kb + (lin >> 4)) * RNK + (lin & 15)];
            lin = t + 256;
            Ws[lin >> 4][lin & 15] = wg[(size_t)(kb + (lin >> 4)) * RNK + (lin & 15)];
        }
        __syncthreads();
#pragma unroll
        for (int kk = 0; kk < 32; kk++) {
            float xv = xr[kb + kk];
#pragma unroll
            for (int u = 0; u < 8; u++) acc[u] += xv * Ws[kk][rh + u];
        }
    }
    if (valid) {
        float* dst = g_Ascr + (size_t)(row0 + row) * RNK + rh;
#pragma unroll
        for (int u = 0; u < 8; u++) dst[u] = SCALEF * acc[u];
    }
}

// ---------------- kernel 2: A tile images (fp16, swizzled) ----------------
__global__ __launch_bounds__(256) void prepA_kernel(const float* __restrict__ x) {
    int tile = blockIdx.x, ci = blockIdx.y;
    int rows = g_tile_rows[tile];
    if (rows == 0) return;
    int row0 = g_tile_row0[tile];
    int t = threadIdx.x;
    int kq = (t & 7) * 8;
    uint4* base = gA + ((size_t)(tile * NCHUNK + ci)) * CHUNK_U4;
#pragma unroll
    for (int it = 0; it < 4; it++) {
        int r = (t >> 3) + it * 32;
        float v[8];
        if (r < rows) {
            const float* p = x + (size_t)(row0 + r) * DIN + ci * KC + kq;
            float4 a = *(const float4*)p;
            float4 b = *(const float4*)(p + 4);
            v[0] = a.x; v[1] = a.y; v[2] = a.z; v[3] = a.w;
            v[4] = b.x; v[5] = b.y; v[6] = b.z; v[7] = b.w;
        } else {
#pragma unroll
            for (int j = 0; j < 8; j++) v[j] = 0.f;
        }
        write_img(base, r, kq, v);
    }
}

// ---------------- kernel 3: transpose W_base -> B images [n][k] (fp16, swizzled) ----
__global__ __launch_bounds__(256) void prepB_kernel(const float* __restrict__ Wb) {
    int bx = blockIdx.x;          // g*8 + ncb
    int ci = blockIdx.y;
    int g = bx >> 3, ncb = bx & 7;
    __shared__ float S[KC][129];
    int t = threadIdx.x;
    const float* W = Wb + (size_t)g * DIN * DOUT + (size_t)ci * KC * DOUT + ncb * BN;
    int c4 = (t & 31) * 4;
    int kr0 = t >> 5;
#pragma unroll
    for (int i = 0; i < 8; i++) {
        int kr = kr0 + i * 8;
        float4 v = *(const float4*)(W + (size_t)kr * DOUT + c4);
        S[kr][c4 + 0] = v.x; S[kr][c4 + 1] = v.y;
        S[kr][c4 + 2] = v.z; S[kr][c4 + 3] = v.w;
    }
    __syncthreads();
    int kq = (t & 7) * 8;
    uint4* base = gB + ((size_t)(bx * NCHUNK + ci)) * CHUNK_U4;
#pragma unroll
    for (int it = 0; it < 4; it++) {
        int r = (t >> 3) + it * 32;   // n-row
        float v[8];
#pragma unroll
        for (int j = 0; j < 8; j++) v[j] = S[kq + j][r];
        write_img(base, r, kq, v);
    }
}

// ---------------- kernel 4: LoRA chunk images (chunk 16, K=16 -> kq 0,8 only) -------
__global__ __launch_bounds__(256) void prepL_kernel(const float* __restrict__ WBl) {
    int b = blockIdx.x;
    int t = threadIdx.x;
    int r  = t >> 1;          // row (m or n), 0..127
    int kq = (t & 1) * 8;     // only units covering k<16
    if (b < MAX_TILES) {
        int rows = g_tile_rows[b];
        if (rows == 0) return;
        int row0 = g_tile_row0[b];
        uint4* base = gA + ((size_t)(b * NCHUNK + 16)) * CHUNK_U4;
        float v[8];
#pragma unroll
        for (int j = 0; j < 8; j++)
            v[j] = (r < rows) ? g_Ascr[(size_t)(row0 + r) * RNK + kq + j] : 0.f;
        write_img(base, r, kq, v);
    } else {
        int idx = b - MAX_TILES;      // 0..63 : g*8+ncb
        int g = idx >> 3, ncb = idx & 7;
        uint4* base = gB + ((size_t)(idx * NCHUNK + 16)) * CHUNK_U4;
        float v[8];
#pragma unroll
        for (int j = 0; j < 8; j++)
            v[j] = WBl[((size_t)g * RNK + kq + j) * DOUT + ncb * BN + r];
        write_img(base, r, kq, v);
    }
}

// ---------------- kernel 5: fp16 1-pass mma.sync GEMM, bulk-copy pipeline -------
__global__ __launch_bounds__(256, 2) void main_gemm(float* __restrict__ out) {
    int tile = blockIdx.x;
    int rows = g_tile_rows[tile];
    if (rows == 0) return;
    int row0 = g_tile_row0[tile];
    int grp  = g_tile_grp[tile];
    int ncb  = blockIdx.y;
    int col0 = ncb * BN;

    extern __shared__ char smem[];
    __shared__ __align__(16) uint64_t mbar[2];
    uint32_t sbase = smem_u32(smem);
    int t = threadIdx.x;
    int lane = t & 31, warp = t >> 5;
    int wm = warp & 3;        // m-quadrant
    int wn = warp >> 2;       // n-half

    uint32_t mbs[2] = {smem_u32(&mbar[0]), smem_u32(&mbar[1])};
    if (t == 0) {
        MBARRIER_INIT(mbs[0], 1);
        MBARRIER_INIT(mbs[1], 1);
    }
    __syncthreads();

    const uint4* srcA = gA + (size_t)tile * NCHUNK * CHUNK_U4;
    const uint4* srcB = gB + (size_t)(grp * 8 + ncb) * NCHUNK * CHUNK_U4;

    if (t == 0) {
        MBARRIER_EXPECT_TX(mbs[0], STAGE_B);
        CP_BULK(sbase,         (const void*)srcA, MAT_B, mbs[0]);
        CP_BULK(sbase + MAT_B, (const void*)srcB, MAT_B, mbs[0]);
        MBARRIER_EXPECT_TX(mbs[1], STAGE_B);
        CP_BULK(sbase + STAGE_B,         (const void*)(srcA + CHUNK_U4), MAT_B, mbs[1]);
        CP_BULK(sbase + STAGE_B + MAT_B, (const void*)(srcB + CHUNK_U4), MAT_B, mbs[1]);
    }

    // per-thread fragment address components (swizzled layout)
    int lr = lane & 15;
    int hf = lane >> 4;       // +8 k-elements half
    uint32_t rowA[2], swA[2], rowB[4], swB[4];
#pragma unroll
    for (int i = 0; i < 2; i++) {
        int rr = wm * 32 + i * 16 + lr;
        rowA[i] = (uint32_t)rr * 128u;
        swA[i]  = (uint32_t)(rr & 7);
    }
#pragma unroll
    for (int jp = 0; jp < 4; jp++) {
        int rr = wn * 64 + jp * 16 + lr;
        rowB[jp] = (uint32_t)rr * 128u;
        swB[jp]  = (uint32_t)(rr & 7);
    }

    float acc[2][8][4];
#pragma unroll
    for (int i = 0; i < 2; i++)
#pragma unroll
        for (int j = 0; j < 8; j++)
#pragma unroll
            for (int q = 0; q < 4; q++) acc[i][j][q] = 0.f;

    for (int ci = 0; ci < NCHUNK; ci++) {
        int s = ci & 1;
        MBARRIER_WAIT_PARITY(mbs[s], (ci >> 1) & 1);

        uint32_t stg = sbase + (uint32_t)s * STAGE_B;
        int ksteps = (ci == NCHUNK - 1) ? 1 : 4;   // LoRA chunk: K=16 = 1 kstep
        for (int ks = 0; ks < ksteps; ks++) {
            uint32_t u = (uint32_t)(ks * 2 + hf);
            uint32_t aF[2][4];
#pragma unroll
            for (int i = 0; i < 2; i++)
                ldm_x4(aF[i], stg + rowA[i] + ((u ^ swA[i]) << 4));
            uint32_t bF[4][4];
#pragma unroll
            for (int jp = 0; jp < 4; jp++)
                ldm_x4(bF[jp], stg + MAT_B + rowB[jp] + ((u ^ swB[jp]) << 4));
#pragma unroll
            for (int i = 0; i < 2; i++)
#pragma unroll
                for (int jp = 0; jp < 4; jp++)
#pragma unroll
                    for (int w2 = 0; w2 < 2; w2++) {
                        int j = jp * 2 + w2;
                        mma_f16(acc[i][j], aF[i], bF[jp][w2], bF[jp][w2 + 2]);
                    }
        }
        __syncthreads();
        if (t == 0 && ci + 2 < NCHUNK) {
            MBARRIER_EXPECT_TX(mbs[s], STAGE_B);
            CP_BULK(stg,         (const void*)(srcA + (size_t)(ci + 2) * CHUNK_U4), MAT_B, mbs[s]);
            CP_BULK(stg + MAT_B, (const void*)(srcB + (size_t)(ci + 2) * CHUNK_U4), MAT_B, mbs[s]);
        }
    }

    // ---- epilogue: direct stores (each element written exactly once) ----
    int lr4 = lane >> 2;
    int lc2 = 2 * (lane & 3);
#pragma unroll
    for (int i = 0; i < 2; i++) {
        int mloc0 = wm * 32 + i * 16 + lr4;
#pragma unroll
        for (int j = 0; j < 8; j++) {
            int c = col0 + wn * 64 + j * 8 + lc2;
            if (mloc0 < rows) {
                float2 v = make_float2(acc[i][j][0], acc[i][j][1]);
                *(float2*)(out + (size_t)(row0 + mloc0) * DOUT + c) = v;
            }
            if (mloc0 + 8 < rows) {
                float2 v = make_float2(acc[i][j][2], acc[i][j][3]);
                *(float2*)(out + (size_t)(row0 + mloc0 + 8) * DOUT + c) = v;
            }
        }
    }
}

// ---------------- launch ----------------
extern "C" void kernel_launch(void* const* d_in, const int* in_sizes, int n_in,
                              void* d_out, int out_size) {
    const float* x   = (const float*)d_in[0];
    const int*   xg  = (const int*)d_in[1];   // x_groups (int32, int64-hedged)
    const float* Wb  = (const float*)d_in[2]; // [G, DIN, DOUT]
    const float* WA  = (const float*)d_in[3]; // [G, DIN, R]
    const float* WBl = (const float*)d_in[4]; // [G, R, DOUT]
    float* out = (float*)d_out;

    int N = in_sizes[0] / DIN;
    int maxTiles = (N + BM - 1) / BM + GNUM;

    cudaFuncSetAttribute(main_gemm, cudaFuncAttributeMaxDynamicSharedMemorySize, SMEM_MAIN);

    setup_kernel<<<1, 256>>>(xg, N);
    lora_a_kernel<<<maxTiles, 256>>>(x, WA);
    dim3 ga(maxTiles, 16);
    prepA_kernel<<<ga, 256>>>(x);
    dim3 gb(GNUM * 8, 16);
    prepB_kernel<<<gb, 256>>>(Wb);
    prepL_kernel<<<maxTiles + GNUM * 8, 256>>>(WBl);
    dim3 gm(maxTiles, DOUT / BN);
    main_gemm<<<gm, 256, SMEM_MAIN>>>(out);
}

// round 11
// speedup vs baseline: 2.7855x; 1.0227x over previous
#include <cuda_runtime.h>
#include <cuda_fp16.h>
#include <cstdint>

#define GNUM 8
#define DIN 1024
#define DOUT 1024
#define RNK 16
#define SCALEF 2.0f

#define BM 128
#define BN 128
#define KC 64                 // K elements per chunk
#define NCHUNK 17             // 16 real K-chunks + 1 LoRA chunk (K=16, 1 kstep)
#define MAX_N 8192
#define MAX_TILES ((MAX_N / BM) + GNUM)   // 72
#define CHUNK_U4 1024         // one 128x64 fp16 matrix image (16KB), in uint4

#define MAT_B 16384
#define STAGE_B 32768         // A image + B image
#define SMEM_MAIN (2 * STAGE_B)   // 64KB -> 2 CTAs/SM

// megaprep block ranges
#define PRE_A   MAX_TILES                    // 72
#define PRE_B   (PRE_A + MAX_TILES * 16)     // 1224
#define PRE_LB  (PRE_B + GNUM * 8 * 16)      // 2248
#define PRE_TOT (PRE_LB + GNUM * 8)          // 2312

// ---------------- device scratch (no allocations allowed) ----------------
__device__ int g_tile_row0[MAX_TILES];
__device__ int g_tile_rows[MAX_TILES];
__device__ int g_tile_grp[MAX_TILES];
__device__ uint4 gA[MAX_TILES * NCHUNK * CHUNK_U4];   // fp16 A images [m][k]
__device__ uint4 gB[GNUM * 8 * NCHUNK * CHUNK_U4];    // fp16 B images [n][k]

// ---------------- PTX helpers (baseline ISA only; no 'a'-features) ----------------
__device__ __forceinline__ uint32_t smem_u32(const void* p) {
    uint32_t a;
    asm("{ .reg .u64 t; cvta.to.shared.u64 t, %1; cvt.u32.u64 %0, t; }" : "=r"(a) : "l"(p));
    return a;
}
#define MBARRIER_INIT(a, c) \
    asm volatile("mbarrier.init.shared.b64 [%0], %1;" :: "r"((uint32_t)(a)), "r"((uint32_t)(c)) : "memory")
#define MBARRIER_EXPECT_TX(a, tx) \
    asm volatile("mbarrier.arrive.expect_tx.shared.b64 _, [%0], %1;" \
                 :: "r"((uint32_t)(a)), "r"((uint32_t)(tx)) : "memory")
#define MBARRIER_WAIT_PARITY(a, ph) do { \
    uint32_t _m = (uint32_t)(a); uint32_t _p = (uint32_t)(ph); uint32_t _d; \
    asm volatile("{\n\t.reg .pred p;\n\t" \
        "mbarrier.try_wait.parity.acquire.cta.shared::cta.b64 p, [%1], %2;\n\t" \
        "selp.b32 %0, 1, 0, p;\n\t}" : "=r"(_d) : "r"(_m), "r"(_p) : "memory"); \
    if (!_d) { \
        asm volatile("{\n\t.reg .pred P1;\n\t" \
            "WL_%=:\n\t" \
            "mbarrier.try_wait.parity.acquire.cta.shared::cta.b64 P1, [%0], %1, 0x989680;\n\t" \
            "@P1 bra.uni WD_%=;\n\tbra.uni WL_%=;\n\tWD_%=:\n\t}" \
            :: "r"(_m), "r"(_p) : "memory"); \
    } } while (0)
#define CP_BULK(dst, src, bytes, mb) \
    asm volatile("cp.async.bulk.shared::cluster.global.mbarrier::complete_tx::bytes " \
                 "[%0], [%1], %2, [%3];" \
                 :: "r"((uint32_t)(dst)), "l"(src), "r"((uint32_t)(bytes)), \
                    "r"((uint32_t)(mb)) : "memory")

__device__ __forceinline__ void ldm_x4(uint32_t* r, uint32_t addr) {
    asm volatile("ldmatrix.sync.aligned.m8n8.x4.shared.b16 {%0,%1,%2,%3}, [%4];"
                 : "=r"(r[0]), "=r"(r[1]), "=r"(r[2]), "=r"(r[3]) : "r"(addr));
}
__device__ __forceinline__ void mma_f16(float* d, const uint32_t* a, uint32_t b0, uint32_t b1) {
    asm volatile("mma.sync.aligned.m16n8k16.row.col.f32.f16.f16.f32 "
                 "{%0,%1,%2,%3}, {%4,%5,%6,%7}, {%8,%9}, {%0,%1,%2,%3};"
                 : "+f"(d[0]), "+f"(d[1]), "+f"(d[2]), "+f"(d[3])
                 : "r"(a[0]), "r"(a[1]), "r"(a[2]), "r"(a[3]), "r"(b0), "r"(b1));
}

// ---------------- fp16 pack + swizzled image write ----------------
__device__ __forceinline__ uint4 pack8h(const float* v) {
    uint32_t h[4];
#pragma unroll
    for (int p = 0; p < 4; p++) {
        __half2 hp = __floats2half2_rn(v[2 * p], v[2 * p + 1]);
        h[p] = *reinterpret_cast<uint32_t*>(&hp);
    }
    return make_uint4(h[0], h[1], h[2], h[3]);
}
__device__ __forceinline__ void write_img(uint4* base, int row, int kq, const float* v) {
    uint32_t s = (uint32_t)row * 8u + (((uint32_t)kq >> 3) ^ ((uint32_t)row & 7u));
    base[s] = pack8h(v);
}

__device__ __forceinline__ int get_group(const int* p, int i, int is64) {
    return is64 ? p[2 * i] : p[i];
}

// cooperative group-boundary search: st[0..8] = starts, st[9] = is64 flag
__device__ __forceinline__ void find_starts(const int* gr, int N, int* st) {
    int t = threadIdx.x;
    if (t == 0) {
        int wl = gr[N - 1], wp = gr[N - 2];
        st[GNUM + 1] = (wl == 0 && wp != 0) ? 1 : 0;   // int64 dtype hedge
    }
    __syncthreads();
    int is64 = st[GNUM + 1];
    if (t <= GNUM) {
        int lo = 0, hi = N;
        while (lo < hi) {
            int mid = (lo + hi) >> 1;
            if (get_group(gr, mid, is64) < t) lo = mid + 1;
            else hi = mid;
        }
        st[t] = lo;
    }
    __syncthreads();
}

__device__ __forceinline__ bool tile_info(const int* st, int tile,
                                          int& row0, int& rows, int& grp) {
    int nt = 0;
#pragma unroll
    for (int g = 0; g < GNUM; g++) {
        int s = st[g], e = st[g + 1];
        int cnt = (e - s + BM - 1) / BM;
        if (tile < nt + cnt) {
            row0 = s + (tile - nt) * BM;
            rows = min(BM, e - row0);
            grp = g;
            return true;
        }
        nt += cnt;
    }
    return false;
}

// ---------------- kernel 1: fused prep (lora_a->image, A images, B images, LoRA-B) ---
__global__ __launch_bounds__(256) void megaprep(const float* __restrict__ x,
                                                const float* __restrict__ Wb,
                                                const float* __restrict__ WA,
                                                const float* __restrict__ WBl,
                                                const int* __restrict__ gr, int N) {
    __shared__ __align__(16) float S[KC][129];
    __shared__ int s_start[GNUM + 2];
    int b = blockIdx.x;
    int t = threadIdx.x;

    if (b < PRE_A) {
        // ---- LoRA-A block for tile b: compute SCALE*(x@W_A[g]) -> fp16 image chunk 16
        find_starts(gr, N, s_start);
        if (b == 0 && t < MAX_TILES) {          // publish tile table for main_gemm
            int r0, rw, gp;
            if (tile_info(s_start, t, r0, rw, gp)) {
                g_tile_row0[t] = r0; g_tile_rows[t] = rw; g_tile_grp[t] = gp;
            } else {
                g_tile_rows[t] = 0;
            }
        }
        int row0, rows, grp;
        if (!tile_info(s_start, b, row0, rows, grp)) return;

        int row = t >> 1;
        int rh  = (t & 1) * 8;
        bool valid = row < rows;
        const float* xr = x + (size_t)(row0 + (valid ? row : 0)) * DIN;
        const float* wg = WA + (size_t)grp * DIN * RNK;
        float (*Ws)[RNK] = reinterpret_cast<float (*)[RNK]>(&S[0][0]);

        float acc[8] = {0.f, 0.f, 0.f, 0.f, 0.f, 0.f, 0.f, 0.f};
        for (int kb = 0; kb < DIN; kb += 32) {
            __syncthreads();
            {
                int lin = t;
                Ws[lin >> 4][lin & 15] = wg[(size_t)(kb + (lin >> 4)) * RNK + (lin & 15)];
                lin = t + 256;
                Ws[lin >> 4][lin & 15] = wg[(size_t)(kb + (lin >> 4)) * RNK + (lin & 15)];
            }
            __syncthreads();
#pragma unroll
            for (int kk = 0; kk < 32; kk++) {
                float xv = xr[kb + kk];
#pragma unroll
                for (int u = 0; u < 8; u++) acc[u] += xv * Ws[kk][rh + u];
            }
        }
        float v[8];
#pragma unroll
        for (int u = 0; u < 8; u++) v[u] = valid ? SCALEF * acc[u] : 0.f;
        uint4* base = gA + ((size_t)(b * NCHUNK + 16)) * CHUNK_U4;
        write_img(base, row, rh, v);           // only k-units 0,1 are read for chunk 16
    } else if (b < PRE_B) {
        // ---- A tile image (fp16, swizzled): tile, chunk ci
        find_starts(gr, N, s_start);
        int idx = b - PRE_A;
        int tile = idx >> 4, ci = idx & 15;
        int row0, rows, grp;
        if (!tile_info(s_start, tile, row0, rows, grp)) return;

        int kq = (t & 7) * 8;
        uint4* base = gA + ((size_t)(tile * NCHUNK + ci)) * CHUNK_U4;
#pragma unroll
        for (int it = 0; it < 4; it++) {
            int r = (t >> 3) + it * 32;
            float v[8];
            if (r < rows) {
                const float* p = x + (size_t)(row0 + r) * DIN + ci * KC + kq;
                float4 a = *(const float4*)p;
                float4 c = *(const float4*)(p + 4);
                v[0] = a.x; v[1] = a.y; v[2] = a.z; v[3] = a.w;
                v[4] = c.x; v[5] = c.y; v[6] = c.z; v[7] = c.w;
            } else {
#pragma unroll
                for (int j = 0; j < 8; j++) v[j] = 0.f;
            }
            write_img(base, r, kq, v);
        }
    } else if (b < PRE_LB) {
        // ---- B image: transpose W_base[g] chunk ci, cols [ncb*128, +128) -> [n][k]
        int idx = b - PRE_B;
        int bx = idx >> 4, ci = idx & 15;      // bx = g*8 + ncb
        int g = bx >> 3, ncb = bx & 7;
        const float* W = Wb + (size_t)g * DIN * DOUT + (size_t)ci * KC * DOUT + ncb * BN;
        int c4 = (t & 31) * 4;
        int kr0 = t >> 5;
#pragma unroll
        for (int i = 0; i < 8; i++) {
            int kr = kr0 + i * 8;
            float4 v = *(const float4*)(W + (size_t)kr * DOUT + c4);
            S[kr][c4 + 0] = v.x; S[kr][c4 + 1] = v.y;
            S[kr][c4 + 2] = v.z; S[kr][c4 + 3] = v.w;
        }
        __syncthreads();
        int kq = (t & 7) * 8;
        uint4* base = gB + ((size_t)(bx * NCHUNK + ci)) * CHUNK_U4;
#pragma unroll
        for (int it = 0; it < 4; it++) {
            int r = (t >> 3) + it * 32;        // n-row
            float v[8];
#pragma unroll
            for (int j = 0; j < 8; j++) v[j] = S[kq + j][r];
            write_img(base, r, kq, v);
        }
    } else {
        // ---- LoRA-B image (chunk 16): W_B[g][k][n] -> [n][k], k<16
        int idx = b - PRE_LB;                  // 0..63 : g*8+ncb
        int g = idx >> 3, ncb = idx & 7;
        int r  = t >> 1;
        int kq = (t & 1) * 8;
        uint4* base = gB + ((size_t)(idx * NCHUNK + 16)) * CHUNK_U4;
        float v[8];
#pragma unroll
        for (int j = 0; j < 8; j++)
            v[j] = WBl[((size_t)g * RNK + kq + j) * DOUT + ncb * BN + r];
        write_img(base, r, kq, v);
    }
}

// ---------------- kernel 2: fp16 1-pass mma.sync GEMM, bulk-copy pipeline -------
__global__ __launch_bounds__(256, 2) void main_gemm(float* __restrict__ out) {
    int tile = blockIdx.x;
    int rows = g_tile_rows[tile];
    if (rows == 0) return;
    int row0 = g_tile_row0[tile];
    int grp  = g_tile_grp[tile];
    int ncb  = blockIdx.y;
    int col0 = ncb * BN;

    extern __shared__ char smem[];
    __shared__ __align__(16) uint64_t mbar[2];
    uint32_t sbase = smem_u32(smem);
    int t = threadIdx.x;
    int lane = t & 31, warp = t >> 5;
    int wm = warp & 3;        // m-quadrant
    int wn = warp >> 2;       // n-half

    uint32_t mbs[2] = {smem_u32(&mbar[0]), smem_u32(&mbar[1])};
    if (t == 0) {
        MBARRIER_INIT(mbs[0], 1);
        MBARRIER_INIT(mbs[1], 1);
    }
    __syncthreads();

    const uint4* srcA = gA + (size_t)tile * NCHUNK * CHUNK_U4;
    const uint4* srcB = gB + (size_t)(grp * 8 + ncb) * NCHUNK * CHUNK_U4;

    if (t == 0) {
        MBARRIER_EXPECT_TX(mbs[0], STAGE_B);
        CP_BULK(sbase,         (const void*)srcA, MAT_B, mbs[0]);
        CP_BULK(sbase + MAT_B, (const void*)srcB, MAT_B, mbs[0]);
        MBARRIER_EXPECT_TX(mbs[1], STAGE_B);
        CP_BULK(sbase + STAGE_B,         (const void*)(srcA + CHUNK_U4), MAT_B, mbs[1]);
        CP_BULK(sbase + STAGE_B + MAT_B, (const void*)(srcB + CHUNK_U4), MAT_B, mbs[1]);
    }

    // per-thread fragment address components (swizzled layout)
    int lr = lane & 15;
    int hf = lane >> 4;       // +8 k-elements half
    uint32_t rowA[2], swA[2], rowB[4], swB[4];
#pragma unroll
    for (int i = 0; i < 2; i++) {
        int rr = wm * 32 + i * 16 + lr;
        rowA[i] = (uint32_t)rr * 128u;
        swA[i]  = (uint32_t)(rr & 7);
    }
#pragma unroll
    for (int jp = 0; jp < 4; jp++) {
        int rr = wn * 64 + jp * 16 + lr;
        rowB[jp] = (uint32_t)rr * 128u;
        swB[jp]  = (uint32_t)(rr & 7);
    }

    float acc[2][8][4];
#pragma unroll
    for (int i = 0; i < 2; i++)
#pragma unroll
        for (int j = 0; j < 8; j++)
#pragma unroll
            for (int q = 0; q < 4; q++) acc[i][j][q] = 0.f;

    for (int ci = 0; ci < NCHUNK; ci++) {
        int s = ci & 1;
        MBARRIER_WAIT_PARITY(mbs[s], (ci >> 1) & 1);

        uint32_t stg = sbase + (uint32_t)s * STAGE_B;
        int ksteps = (ci == NCHUNK - 1) ? 1 : 4;   // LoRA chunk: K=16 = 1 kstep
        for (int ks = 0; ks < ksteps; ks++) {
            uint32_t u = (uint32_t)(ks * 2 + hf);
            uint32_t aF[2][4];
#pragma unroll
            for (int i = 0; i < 2; i++)
                ldm_x4(aF[i], stg + rowA[i] + ((u ^ swA[i]) << 4));
            uint32_t bF[4][4];
#pragma unroll
            for (int jp = 0; jp < 4; jp++)
                ldm_x4(bF[jp], stg + MAT_B + rowB[jp] + ((u ^ swB[jp]) << 4));
#pragma unroll
            for (int i = 0; i < 2; i++)
#pragma unroll
                for (int jp = 0; jp < 4; jp++)
#pragma unroll
                    for (int w2 = 0; w2 < 2; w2++) {
                        int j = jp * 2 + w2;
                        mma_f16(acc[i][j], aF[i], bF[jp][w2], bF[jp][w2 + 2]);
                    }
        }
        __syncthreads();
        if (t == 0 && ci + 2 < NCHUNK) {
            MBARRIER_EXPECT_TX(mbs[s], STAGE_B);
            CP_BULK(stg,         (const void*)(srcA + (size_t)(ci + 2) * CHUNK_U4), MAT_B, mbs[s]);
            CP_BULK(stg + MAT_B, (const void*)(srcB + (size_t)(ci + 2) * CHUNK_U4), MAT_B, mbs[s]);
        }
    }

    // ---- epilogue: direct stores (each element written exactly once) ----
    int lr4 = lane >> 2;
    int lc2 = 2 * (lane & 3);
#pragma unroll
    for (int i = 0; i < 2; i++) {
        int mloc0 = wm * 32 + i * 16 + lr4;
#pragma unroll
        for (int j = 0; j < 8; j++) {
            int c = col0 + wn * 64 + j * 8 + lc2;
            if (mloc0 < rows) {
                float2 v = make_float2(acc[i][j][0], acc[i][j][1]);
                *(float2*)(out + (size_t)(row0 + mloc0) * DOUT + c) = v;
            }
            if (mloc0 + 8 < rows) {
                float2 v = make_float2(acc[i][j][2], acc[i][j][3]);
                *(float2*)(out + (size_t)(row0 + mloc0 + 8) * DOUT + c) = v;
            }
        }
    }
}

// ---------------- launch ----------------
extern "C" void kernel_launch(void* const* d_in, const int* in_sizes, int n_in,
                              void* d_out, int out_size) {
    const float* x   = (const float*)d_in[0];
    const int*   xg  = (const int*)d_in[1];   // x_groups (int32, int64-hedged)
    const float* Wb  = (const float*)d_in[2]; // [G, DIN, DOUT]
    const float* WA  = (const float*)d_in[3]; // [G, DIN, R]
    const float* WBl = (const float*)d_in[4]; // [G, R, DOUT]
    float* out = (float*)d_out;

    int N = in_sizes[0] / DIN;

    cudaFuncSetAttribute(main_gemm, cudaFuncAttributeMaxDynamicSharedMemorySize, SMEM_MAIN);

    megaprep<<<PRE_TOT, 256>>>(x, Wb, WA, WBl, xg, N);
    dim3 gm(MAX_TILES, DOUT / BN);
    main_gemm<<<gm, 256, SMEM_MAIN>>>(out);
}

// round 12
// speedup vs baseline: 3.8433x; 1.3798x over previous
#include <cuda_runtime.h>
#include <cuda_fp16.h>
#include <cstdint>

#define GNUM 8
#define DIN 1024
#define DOUT 1024
#define RNK 16
#define SCALEF 2.0f

#define BM 128
#define BN 128
#define KC 64                 // K elements per chunk
#define NCHUNK 17             // 16 real K-chunks + 1 LoRA chunk (K=16, 1 kstep)
#define MAX_N 8192
#define MAX_TILES ((MAX_N / BM) + GNUM)   // 72
#define CHUNK_U4 1024         // one 128x64 fp16 matrix image (16KB), in uint4

#define MAT_B 16384
#define STAGE_B 32768         // A image + B image
#define SMEM_MAIN (2 * STAGE_B)   // 64KB -> 2 CTAs/SM

// megaprep block ranges
#define PRE_A   (MAX_TILES * 2)              // 144  (LoRA-A, 2 blocks/tile)
#define PRE_B   (PRE_A + MAX_TILES * 16)     // 1296 (A images)
#define PRE_LB  (PRE_B + GNUM * 8 * 16)      // 2320 (B images)
#define PRE_TOT (PRE_LB + GNUM * 8)          // 2384 (LoRA-B images)

// ---------------- device scratch (no allocations allowed) ----------------
__device__ int g_tile_row0[MAX_TILES];
__device__ int g_tile_rows[MAX_TILES];
__device__ int g_tile_grp[MAX_TILES];
__device__ uint4 gA[MAX_TILES * NCHUNK * CHUNK_U4];   // fp16 A images [m][k]
__device__ uint4 gB[GNUM * 8 * NCHUNK * CHUNK_U4];    // fp16 B images [n][k]

// ---------------- PTX helpers (baseline ISA only; no 'a'-features) ----------------
__device__ __forceinline__ uint32_t smem_u32(const void* p) {
    uint32_t a;
    asm("{ .reg .u64 t; cvta.to.shared.u64 t, %1; cvt.u32.u64 %0, t; }" : "=r"(a) : "l"(p));
    return a;
}
#define MBARRIER_INIT(a, c) \
    asm volatile("mbarrier.init.shared.b64 [%0], %1;" :: "r"((uint32_t)(a)), "r"((uint32_t)(c)) : "memory")
#define MBARRIER_EXPECT_TX(a, tx) \
    asm volatile("mbarrier.arrive.expect_tx.shared.b64 _, [%0], %1;" \
                 :: "r"((uint32_t)(a)), "r"((uint32_t)(tx)) : "memory")
#define MBARRIER_WAIT_PARITY(a, ph) do { \
    uint32_t _m = (uint32_t)(a); uint32_t _p = (uint32_t)(ph); uint32_t _d; \
    asm volatile("{\n\t.reg .pred p;\n\t" \
        "mbarrier.try_wait.parity.acquire.cta.shared::cta.b64 p, [%1], %2;\n\t" \
        "selp.b32 %0, 1, 0, p;\n\t}" : "=r"(_d) : "r"(_m), "r"(_p) : "memory"); \
    if (!_d) { \
        asm volatile("{\n\t.reg .pred P1;\n\t" \
            "WL_%=:\n\t" \
            "mbarrier.try_wait.parity.acquire.cta.shared::cta.b64 P1, [%0], %1, 0x989680;\n\t" \
            "@P1 bra.uni WD_%=;\n\tbra.uni WL_%=;\n\tWD_%=:\n\t}" \
            :: "r"(_m), "r"(_p) : "memory"); \
    } } while (0)
#define CP_BULK(dst, src, bytes, mb) \
    asm volatile("cp.async.bulk.shared::cluster.global.mbarrier::complete_tx::bytes " \
                 "[%0], [%1], %2, [%3];" \
                 :: "r"((uint32_t)(dst)), "l"(src), "r"((uint32_t)(bytes)), \
                    "r"((uint32_t)(mb)) : "memory")

__device__ __forceinline__ void ldm_x4(uint32_t* r, uint32_t addr) {
    asm volatile("ldmatrix.sync.aligned.m8n8.x4.shared.b16 {%0,%1,%2,%3}, [%4];"
                 : "=r"(r[0]), "=r"(r[1]), "=r"(r[2]), "=r"(r[3]) : "r"(addr));
}
__device__ __forceinline__ void mma_f16(float* d, const uint32_t* a, uint32_t b0, uint32_t b1) {
    asm volatile("mma.sync.aligned.m16n8k16.row.col.f32.f16.f16.f32 "
                 "{%0,%1,%2,%3}, {%4,%5,%6,%7}, {%8,%9}, {%0,%1,%2,%3};"
                 : "+f"(d[0]), "+f"(d[1]), "+f"(d[2]), "+f"(d[3])
                 : "r"(a[0]), "r"(a[1]), "r"(a[2]), "r"(a[3]), "r"(b0), "r"(b1));
}

// ---------------- fp16 pack + swizzled image write ----------------
__device__ __forceinline__ uint4 pack8h(const float* v) {
    uint32_t h[4];
#pragma unroll
    for (int p = 0; p < 4; p++) {
        __half2 hp = __floats2half2_rn(v[2 * p], v[2 * p + 1]);
        h[p] = *reinterpret_cast<uint32_t*>(&hp);
    }
    return make_uint4(h[0], h[1], h[2], h[3]);
}
__device__ __forceinline__ void write_img(uint4* base, int row, int kq, const float* v) {
    uint32_t s = (uint32_t)row * 8u + (((uint32_t)kq >> 3) ^ ((uint32_t)row & 7u));
    base[s] = pack8h(v);
}

__device__ __forceinline__ int get_group(const int* p, int i, int is64) {
    return is64 ? p[2 * i] : p[i];
}

// cooperative group-boundary search: st[0..8] = starts, st[9] = is64 flag
__device__ __forceinline__ void find_starts(const int* gr, int N, int* st) {
    int t = threadIdx.x;
    if (t == 0) {
        int wl = gr[N - 1], wp = gr[N - 2];
        st[GNUM + 1] = (wl == 0 && wp != 0) ? 1 : 0;   // int64 dtype hedge
    }
    __syncthreads();
    int is64 = st[GNUM + 1];
    if (t <= GNUM) {
        int lo = 0, hi = N;
        while (lo < hi) {
            int mid = (lo + hi) >> 1;
            if (get_group(gr, mid, is64) < t) lo = mid + 1;
            else hi = mid;
        }
        st[t] = lo;
    }
    __syncthreads();
}

__device__ __forceinline__ bool tile_info(const int* st, int tile,
                                          int& row0, int& rows, int& grp) {
    int nt = 0;
#pragma unroll
    for (int g = 0; g < GNUM; g++) {
        int s = st[g], e = st[g + 1];
        int cnt = (e - s + BM - 1) / BM;
        if (tile < nt + cnt) {
            row0 = s + (tile - nt) * BM;
            rows = min(BM, e - row0);
            grp = g;
            return true;
        }
        nt += cnt;
    }
    return false;
}

// ---------------- kernel 1: fused prep (lora_a->image, A images, B images, LoRA-B) ---
__global__ __launch_bounds__(256) void megaprep(const float* __restrict__ x,
                                                const float* __restrict__ Wb,
                                                const float* __restrict__ WA,
                                                const float* __restrict__ WBl,
                                                const int* __restrict__ gr, int N) {
    __shared__ __align__(16) float S[KC][129];
    __shared__ int s_start[GNUM + 2];
    int b = blockIdx.x;
    int t = threadIdx.x;

    if (b < PRE_A) {
        // ---- LoRA-A: SCALE*(x@W_A[g]) -> fp16 image chunk 16; 2 blocks/tile, 64 rows each
        find_starts(gr, N, s_start);
        if (b == 0 && t < MAX_TILES) {          // publish tile table for main_gemm
            int r0, rw, gp;
            if (tile_info(s_start, t, r0, rw, gp)) {
                g_tile_row0[t] = r0; g_tile_rows[t] = rw; g_tile_grp[t] = gp;
            } else {
                g_tile_rows[t] = 0;
            }
        }
        int tile = b >> 1, half = b & 1;
        int row0, rows, grp;
        if (!tile_info(s_start, tile, row0, rows, grp)) return;

        float* Xs = &S[0][0];                   // [64][33] padded
        float* Ws = Xs + 64 * 33;               // [32][16]
        int rloc = t >> 2;                      // 0..63 local row
        int rq   = (t & 3) * 4;                 // 4 of 16 r-outputs
        int mrow = half * 64 + rloc;            // row within tile
        const float* wg = WA + (size_t)grp * DIN * RNK;

        float acc[4] = {0.f, 0.f, 0.f, 0.f};
        for (int kb = 0; kb < DIN; kb += 32) {
            __syncthreads();
            if (t < 128) {                      // Ws chunk [32][16]
                int kk = t >> 2, c = (t & 3) * 4;
                *(float4*)&Ws[kk * 16 + c] =
                    *(const float4*)(wg + (size_t)(kb + kk) * RNK + c);
            }
            {                                   // Xs chunk [64][32], coalesced
                int r = t >> 2;
                int c0 = (t & 3) * 8;
                int grow = half * 64 + r;
                if (grow < rows) {
                    const float* p = x + (size_t)(row0 + grow) * DIN + kb + c0;
                    float4 a = *(const float4*)p;
                    float4 c = *(const float4*)(p + 4);
                    float* d = &Xs[r * 33 + c0];
                    d[0] = a.x; d[1] = a.y; d[2] = a.z; d[3] = a.w;
                    d[4] = c.x; d[5] = c.y; d[6] = c.z; d[7] = c.w;
                } else {
                    float* d = &Xs[r * 33 + c0];
#pragma unroll
                    for (int j = 0; j < 8; j++) d[j] = 0.f;
                }
            }
            __syncthreads();
#pragma unroll
            for (int kk = 0; kk < 32; kk++) {
                float xv = Xs[rloc * 33 + kk];
#pragma unroll
                for (int u = 0; u < 4; u++) acc[u] += xv * Ws[kk * 16 + rq + u];
            }
        }
        // store 4 fp16 outputs at swizzled position (8B aligned)
        __half2 h0 = __floats2half2_rn(SCALEF * acc[0], SCALEF * acc[1]);
        __half2 h1 = __floats2half2_rn(SCALEF * acc[2], SCALEF * acc[3]);
        uint32_t unit = (uint32_t)rq >> 3;     // 0 or 1
        uint32_t s = (uint32_t)mrow * 8u + (unit ^ ((uint32_t)mrow & 7u));
        char* dst = (char*)(gA + ((size_t)(tile * NCHUNK + 16)) * CHUNK_U4)
                    + s * 16 + (rq & 7) * 2;
        uint2 st2;
        st2.x = *reinterpret_cast<uint32_t*>(&h0);
        st2.y = *reinterpret_cast<uint32_t*>(&h1);
        *(uint2*)dst = st2;
    } else if (b < PRE_B) {
        // ---- A tile image (fp16, swizzled): tile, chunk ci
        find_starts(gr, N, s_start);
        int idx = b - PRE_A;
        int tile = idx >> 4, ci = idx & 15;
        int row0, rows, grp;
        if (!tile_info(s_start, tile, row0, rows, grp)) return;

        int kq = (t & 7) * 8;
        uint4* base = gA + ((size_t)(tile * NCHUNK + ci)) * CHUNK_U4;
#pragma unroll
        for (int it = 0; it < 4; it++) {
            int r = (t >> 3) + it * 32;
            float v[8];
            if (r < rows) {
                const float* p = x + (size_t)(row0 + r) * DIN + ci * KC + kq;
                float4 a = *(const float4*)p;
                float4 c = *(const float4*)(p + 4);
                v[0] = a.x; v[1] = a.y; v[2] = a.z; v[3] = a.w;
                v[4] = c.x; v[5] = c.y; v[6] = c.z; v[7] = c.w;
            } else {
#pragma unroll
                for (int j = 0; j < 8; j++) v[j] = 0.f;
            }
            write_img(base, r, kq, v);
        }
    } else if (b < PRE_LB) {
        // ---- B image: transpose W_base[g] chunk ci, cols [ncb*128, +128) -> [n][k]
        int idx = b - PRE_B;
        int bx = idx >> 4, ci = idx & 15;      // bx = g*8 + ncb
        int g = bx >> 3, ncb = bx & 7;
        const float* W = Wb + (size_t)g * DIN * DOUT + (size_t)ci * KC * DOUT + ncb * BN;
        int c4 = (t & 31) * 4;
        int kr0 = t >> 5;
#pragma unroll
        for (int i = 0; i < 8; i++) {
            int kr = kr0 + i * 8;
            float4 v = *(const float4*)(W + (size_t)kr * DOUT + c4);
            S[kr][c4 + 0] = v.x; S[kr][c4 + 1] = v.y;
            S[kr][c4 + 2] = v.z; S[kr][c4 + 3] = v.w;
        }
        __syncthreads();
        int kq = (t & 7) * 8;
        uint4* base = gB + ((size_t)(bx * NCHUNK + ci)) * CHUNK_U4;
#pragma unroll
        for (int it = 0; it < 4; it++) {
            int r = (t >> 3) + it * 32;        // n-row
            float v[8];
#pragma unroll
            for (int j = 0; j < 8; j++) v[j] = S[kq + j][r];
            write_img(base, r, kq, v);
        }
    } else {
        // ---- LoRA-B image (chunk 16): W_B[g][k][n] -> [n][k], k<16
        int idx = b - PRE_LB;                  // 0..63 : g*8+ncb
        int g = idx >> 3, ncb = idx & 7;
        int r  = t >> 1;
        int kq = (t & 1) * 8;
        uint4* base = gB + ((size_t)(idx * NCHUNK + 16)) * CHUNK_U4;
        float v[8];
#pragma unroll
        for (int j = 0; j < 8; j++)
            v[j] = WBl[((size_t)g * RNK + kq + j) * DOUT + ncb * BN + r];
        write_img(base, r, kq, v);
    }
}

// ---------------- kernel 2: fp16 1-pass mma.sync GEMM, bulk-copy pipeline -------
__global__ __launch_bounds__(256, 2) void main_gemm(float* __restrict__ out) {
    int tile = blockIdx.x;
    int rows = g_tile_rows[tile];
    if (rows == 0) return;
    int row0 = g_tile_row0[tile];
    int grp  = g_tile_grp[tile];
    int ncb  = blockIdx.y;
    int col0 = ncb * BN;

    extern __shared__ char smem[];
    __shared__ __align__(16) uint64_t mbar[2];
    uint32_t sbase = smem_u32(smem);
    int t = threadIdx.x;
    int lane = t & 31, warp = t >> 5;
    int wm = warp & 3;        // m-quadrant
    int wn = warp >> 2;       // n-half

    uint32_t mbs[2] = {smem_u32(&mbar[0]), smem_u32(&mbar[1])};
    if (t == 0) {
        MBARRIER_INIT(mbs[0], 1);
        MBARRIER_INIT(mbs[1], 1);
    }
    __syncthreads();

    const uint4* srcA = gA + (size_t)tile * NCHUNK * CHUNK_U4;
    const uint4* srcB = gB + (size_t)(grp * 8 + ncb) * NCHUNK * CHUNK_U4;

    if (t == 0) {
        MBARRIER_EXPECT_TX(mbs[0], STAGE_B);
        CP_BULK(sbase,         (const void*)srcA, MAT_B, mbs[0]);
        CP_BULK(sbase + MAT_B, (const void*)srcB, MAT_B, mbs[0]);
        MBARRIER_EXPECT_TX(mbs[1], STAGE_B);
        CP_BULK(sbase + STAGE_B,         (const void*)(srcA + CHUNK_U4), MAT_B, mbs[1]);
        CP_BULK(sbase + STAGE_B + MAT_B, (const void*)(srcB + CHUNK_U4), MAT_B, mbs[1]);
    }

    // per-thread fragment address components (swizzled layout)
    int lr = lane & 15;
    int hf = lane >> 4;       // +8 k-elements half
    uint32_t rowA[2], swA[2], rowB[4], swB[4];
#pragma unroll
    for (int i = 0; i < 2; i++) {
        int rr = wm * 32 + i * 16 + lr;
        rowA[i] = (uint32_t)rr * 128u;
        swA[i]  = (uint32_t)(rr & 7);
    }
#pragma unroll
    for (int jp = 0; jp < 4; jp++) {
        int rr = wn * 64 + jp * 16 + lr;
        rowB[jp] = (uint32_t)rr * 128u;
        swB[jp]  = (uint32_t)(rr & 7);
    }

    float acc[2][8][4];
#pragma unroll
    for (int i = 0; i < 2; i++)
#pragma unroll
        for (int j = 0; j < 8; j++)
#pragma unroll
            for (int q = 0; q < 4; q++) acc[i][j][q] = 0.f;

    for (int ci = 0; ci < NCHUNK; ci++) {
        int s = ci & 1;
        MBARRIER_WAIT_PARITY(mbs[s], (ci >> 1) & 1);

        uint32_t stg = sbase + (uint32_t)s * STAGE_B;
        int ksteps = (ci == NCHUNK - 1) ? 1 : 4;   // LoRA chunk: K=16 = 1 kstep
        for (int ks = 0; ks < ksteps; ks++) {
            uint32_t u = (uint32_t)(ks * 2 + hf);
            uint32_t aF[2][4];
#pragma unroll
            for (int i = 0; i < 2; i++)
                ldm_x4(aF[i], stg + rowA[i] + ((u ^ swA[i]) << 4));
            uint32_t bF[4][4];
#pragma unroll
            for (int jp = 0; jp < 4; jp++)
                ldm_x4(bF[jp], stg + MAT_B + rowB[jp] + ((u ^ swB[jp]) << 4));
#pragma unroll
            for (int i = 0; i < 2; i++)
#pragma unroll
                for (int jp = 0; jp < 4; jp++)
#pragma unroll
                    for (int w2 = 0; w2 < 2; w2++) {
                        int j = jp * 2 + w2;
                        mma_f16(acc[i][j], aF[i], bF[jp][w2], bF[jp][w2 + 2]);
                    }
        }
        __syncthreads();
        if (t == 0 && ci + 2 < NCHUNK) {
            MBARRIER_EXPECT_TX(mbs[s], STAGE_B);
            CP_BULK(stg,         (const void*)(srcA + (size_t)(ci + 2) * CHUNK_U4), MAT_B, mbs[s]);
            CP_BULK(stg + MAT_B, (const void*)(srcB + (size_t)(ci + 2) * CHUNK_U4), MAT_B, mbs[s]);
        }
    }

    // ---- epilogue: direct stores (each element written exactly once) ----
    int lr4 = lane >> 2;
    int lc2 = 2 * (lane & 3);
#pragma unroll
    for (int i = 0; i < 2; i++) {
        int mloc0 = wm * 32 + i * 16 + lr4;
#pragma unroll
        for (int j = 0; j < 8; j++) {
            int c = col0 + wn * 64 + j * 8 + lc2;
            if (mloc0 < rows) {
                float2 v = make_float2(acc[i][j][0], acc[i][j][1]);
                *(float2*)(out + (size_t)(row0 + mloc0) * DOUT + c) = v;
            }
            if (mloc0 + 8 < rows) {
                float2 v = make_float2(acc[i][j][2], acc[i][j][3]);
                *(float2*)(out + (size_t)(row0 + mloc0 + 8) * DOUT + c) = v;
            }
        }
    }
}

// ---------------- launch ----------------
extern "C" void kernel_launch(void* const* d_in, const int* in_sizes, int n_in,
                              void* d_out, int out_size) {
    const float* x   = (const float*)d_in[0];
    const int*   xg  = (const int*)d_in[1];   // x_groups (int32, int64-hedged)
    const float* Wb  = (const float*)d_in[2]; // [G, DIN, DOUT]
    const float* WA  = (const float*)d_in[3]; // [G, DIN, R]
    const float* WBl = (const float*)d_in[4]; // [G, R, DOUT]
    float* out = (float*)d_out;

    int N = in_sizes[0] / DIN;

    cudaFuncSetAttribute(main_gemm, cudaFuncAttributeMaxDynamicSharedMemorySize, SMEM_MAIN);

    megaprep<<<PRE_TOT, 256>>>(x, Wb, WA, WBl, xg, N);
    dim3 gm(MAX_TILES, DOUT / BN);
    main_gemm<<<gm, 256, SMEM_MAIN>>>(out);
}